// round 13
// baseline (speedup 1.0000x reference)
#include <cuda_runtime.h>
#include <cuda_bf16.h>
#include <cstdint>

#define B 64
#define T 256
#define V 128
#define H 1024
#define G 4096              // 4*H
#define M (B*T)             // 16384
#define NCTA 128

// ---------------- feed-forward mma GEMM tile config (BM64xBN128, 2 CTAs/SM) ----------------
#define GM_BM 64
#define GM_BN 128
#define GM_BK 64
#define GM_A_BYTES (64 * 128)
#define GM_B_BYTES (128 * 128)
#define GM_STAGE (2 * GM_A_BYTES + 2 * GM_B_BYTES)   // 48KB
#define SMEM_GM (2 * GM_STAGE)                       // 96KB -> 2 CTAs/SM

// ---------------- recurrence smem layout (bytes) ----------------
#define SM_W   0
#define SM_Hb  131072
#define SM_RES 196608
#define SMEM_TC (SM_RES + 2 * 64 * 40 * 4)   // 217088

// ---------------- scratch (static device arrays; no cudaMalloc) ----------------
__device__ float g_xg[(size_t)M * G];
__device__ __align__(16) __nv_bfloat16 g_act_hi[(size_t)M * H];
__device__ __align__(16) __nv_bfloat16 g_act_lo[(size_t)M * H];
__device__ __align__(16) __nv_bfloat16 g_w_hi[(size_t)G * H];
__device__ __align__(16) __nv_bfloat16 g_w_lo[(size_t)G * H];
__device__ __align__(16) __nv_bfloat16 g_hb16[2][2][B * H];   // [buf][hi/lo][64*1024]
__device__ unsigned g_arrive[NCTA];      // per-CTA monotone arrival flags
__device__ unsigned g_epoch;             // released by checker warp (CTA 0)

// ---------------- PTX helpers ----------------
__device__ __forceinline__ uint32_t smem_u32(const void* p) {
    uint32_t a;
    asm("{ .reg .u64 t; cvta.to.shared.u64 t, %1; cvt.u32.u64 %0, t; }" : "=r"(a) : "l"(p));
    return a;
}
__device__ __forceinline__ void cp_async16(uint32_t saddr, const void* gaddr) {
    asm volatile("cp.async.cg.shared.global [%0], [%1], 16;" :: "r"(saddr), "l"(gaddr) : "memory");
}
__device__ __forceinline__ void cp_commit() {
    asm volatile("cp.async.commit_group;" ::: "memory");
}
template <int N>
__device__ __forceinline__ void cp_wait() {
    asm volatile("cp.async.wait_group %0;" :: "n"(N) : "memory");
}
__device__ __forceinline__ void ldsm4(uint32_t* r, uint32_t addr) {
    asm volatile("ldmatrix.sync.aligned.m8n8.x4.shared.b16 {%0,%1,%2,%3}, [%4];"
        : "=r"(r[0]), "=r"(r[1]), "=r"(r[2]), "=r"(r[3]) : "r"(addr));
}
__device__ __forceinline__ void mma16816(float* d, const uint32_t* a, const uint32_t* b) {
    asm volatile("mma.sync.aligned.m16n8k16.row.col.f32.bf16.bf16.f32 "
        "{%0,%1,%2,%3}, {%4,%5,%6,%7}, {%8,%9}, {%0,%1,%2,%3};"
        : "+f"(d[0]), "+f"(d[1]), "+f"(d[2]), "+f"(d[3])
        : "r"(a[0]), "r"(a[1]), "r"(a[2]), "r"(a[3]), "r"(b[0]), "r"(b[1]));
}

// ---------------- flag-based grid barrier (no atomics; checker warp in CTA 0) ----------------
__device__ __forceinline__ void gbar2(unsigned target) {
    __threadfence();
    __syncthreads();
    if (threadIdx.x == 0)
        *((volatile unsigned*)&g_arrive[blockIdx.x]) = target;
    if (blockIdx.x == 0) {
        if (threadIdx.x < 32) {
            bool done = false;
            while (!done) {
                bool ok = true;
#pragma unroll
                for (int i = 0; i < 4; ++i) {
                    unsigned v = ((volatile unsigned*)g_arrive)[threadIdx.x * 4 + i];
                    ok &= ((int)(v - target) >= 0);
                }
                done = __all_sync(0xffffffffu, ok);
                if (!done) __nanosleep(32);
            }
            __threadfence();
            if (threadIdx.x == 0) *((volatile unsigned*)&g_epoch) = target;
        }
    } else if (threadIdx.x == 0) {
        while ((int)(*((volatile unsigned*)&g_epoch) - target) < 0) __nanosleep(32);
        __threadfence();
    }
    __syncthreads();
}

// ---------------- fp32 -> bf16 hi/lo split (elementwise) ----------------
__global__ void __launch_bounds__(256) split_bf16(
    const float* __restrict__ in, __nv_bfloat16* __restrict__ hi,
    __nv_bfloat16* __restrict__ lo, int n4)
{
    int i = blockIdx.x * 256 + threadIdx.x;
    if (i >= n4) return;
    float4 v = ((const float4*)in)[i];
    __nv_bfloat16 h0 = __float2bfloat16(v.x);
    __nv_bfloat16 h1 = __float2bfloat16(v.y);
    __nv_bfloat16 h2 = __float2bfloat16(v.z);
    __nv_bfloat16 h3 = __float2bfloat16(v.w);
    __nv_bfloat16 l0 = __float2bfloat16(v.x - __bfloat162float(h0));
    __nv_bfloat16 l1 = __float2bfloat16(v.y - __bfloat162float(h1));
    __nv_bfloat16 l2 = __float2bfloat16(v.z - __bfloat162float(h2));
    __nv_bfloat16 l3 = __float2bfloat16(v.w - __bfloat162float(h3));
    ((__nv_bfloat162*)hi)[2 * i]     = __nv_bfloat162(h0, h1);
    ((__nv_bfloat162*)hi)[2 * i + 1] = __nv_bfloat162(h2, h3);
    ((__nv_bfloat162*)lo)[2 * i]     = __nv_bfloat162(l0, l1);
    ((__nv_bfloat162*)lo)[2 * i + 1] = __nv_bfloat162(l2, l3);
}

// ---------------- split-bf16 tensor GEMM: BM=64, BN=128, 2-stage, 2 CTAs/SM ----------------
__global__ void __launch_bounds__(256, 2) gemm_mma(
    const __nv_bfloat16* __restrict__ Ahi, const __nv_bfloat16* __restrict__ Alo,
    const __nv_bfloat16* __restrict__ Bhi, const __nv_bfloat16* __restrict__ Blo,
    const float* __restrict__ bias, float* __restrict__ C, int Nn, int Kk)
{
    extern __shared__ char smem[];
    const uint32_t sb = smem_u32(smem);
    const int tid  = threadIdx.x;
    const int wid  = tid >> 5;
    const int lane = tid & 31;
    const int m0 = blockIdx.y * GM_BM;
    const int n0 = blockIdx.x * GM_BN;
    const int wm = (wid >> 2) * 32;
    const int wn = (wid & 3) * 32;

    const char* srcs[4];
    srcs[0] = (const char*)(Ahi + (size_t)m0 * Kk);
    srcs[1] = (const char*)(Alo + (size_t)m0 * Kk);
    srcs[2] = (const char*)(Bhi + (size_t)n0 * Kk);
    srcs[3] = (const char*)(Blo + (size_t)n0 * Kk);
    const size_t rstride = (size_t)Kk * 2;
    const int nk = Kk / GM_BK;

    auto load_chunk = [&](int kt, int buf) {
        const uint32_t base = sb + buf * GM_STAGE;
#pragma unroll
        for (int tgt = 0; tgt < 2; ++tgt) {
            const char* gp = srcs[tgt] + (size_t)kt * 128;
            const uint32_t tb = base + tgt * GM_A_BYTES;
#pragma unroll
            for (int p = 0; p < 2; ++p) {
                int idx = tid + p * 256;
                int row = idx >> 3;
                int c16 = (idx & 7) << 4;
                cp_async16(tb + row * 128 + (c16 ^ ((row & 7) << 4)),
                           gp + (size_t)row * rstride + c16);
            }
        }
#pragma unroll
        for (int tgt = 2; tgt < 4; ++tgt) {
            const char* gp = srcs[tgt] + (size_t)kt * 128;
            const uint32_t tb = base + 2 * GM_A_BYTES + (tgt - 2) * GM_B_BYTES;
#pragma unroll
            for (int p = 0; p < 4; ++p) {
                int idx = tid + p * 256;
                int row = idx >> 3;
                int c16 = (idx & 7) << 4;
                cp_async16(tb + row * 128 + (c16 ^ ((row & 7) << 4)),
                           gp + (size_t)row * rstride + c16);
            }
        }
        cp_commit();
    };

    float acc[2][4][4];
#pragma unroll
    for (int i = 0; i < 2; ++i)
#pragma unroll
        for (int j = 0; j < 4; ++j)
#pragma unroll
            for (int k = 0; k < 4; ++k) acc[i][j][k] = 0.f;

    load_chunk(0, 0);

    const int a_row = lane & 15;
    const int a_csel = ((lane >> 4) & 1) << 4;
    const int b_row = (lane & 7) + (((lane >> 4) & 1) << 3);
    const int b_csel = ((lane >> 3) & 1) << 4;

    for (int kt = 0; kt < nk; ++kt) {
        const int buf = kt & 1;
        if (kt + 1 < nk) { load_chunk(kt + 1, buf ^ 1); cp_wait<1>(); }
        else             { cp_wait<0>(); }
        __syncthreads();

        const uint32_t base = sb + buf * GM_STAGE;
        const uint32_t aHiB = base;
        const uint32_t aLoB = base + GM_A_BYTES;
        const uint32_t bHiB = base + 2 * GM_A_BYTES;
        const uint32_t bLoB = bHiB + GM_B_BYTES;

#pragma unroll
        for (int ks = 0; ks < 4; ++ks) {
            const int acol = ks * 32 + a_csel;
            const int bcol = ks * 32 + b_csel;
            uint32_t ahi[2][4], alo[2][4];
#pragma unroll
            for (int mt = 0; mt < 2; ++mt) {
                int row = wm + mt * 16 + a_row;
                uint32_t off = row * 128 + (acol ^ ((row & 7) << 4));
                ldsm4(ahi[mt], aHiB + off);
                ldsm4(alo[mt], aLoB + off);
            }
            uint32_t bhi[2][4], blo[2][4];
#pragma unroll
            for (int np = 0; np < 2; ++np) {
                int row = wn + np * 16 + b_row;
                uint32_t off = row * 128 + (bcol ^ ((row & 7) << 4));
                ldsm4(bhi[np], bHiB + off);
                ldsm4(blo[np], bLoB + off);
            }
#pragma unroll
            for (int mt = 0; mt < 2; ++mt)
#pragma unroll
                for (int np = 0; np < 2; ++np)
#pragma unroll
                    for (int s = 0; s < 2; ++s) {
                        int nt = np * 2 + s;
                        mma16816(acc[mt][nt], ahi[mt], &bhi[np][s * 2]);
                        mma16816(acc[mt][nt], ahi[mt], &blo[np][s * 2]);
                        mma16816(acc[mt][nt], alo[mt], &bhi[np][s * 2]);
                    }
        }
        __syncthreads();
    }

#pragma unroll
    for (int mt = 0; mt < 2; ++mt) {
        const int rg = m0 + wm + mt * 16 + (lane >> 2);
#pragma unroll
        for (int nt = 0; nt < 4; ++nt) {
            const int cg = n0 + wn + nt * 8 + (lane & 3) * 2;
            const float2 bv = *(const float2*)(bias + cg);
            float2 o0, o1;
            o0.x = acc[mt][nt][0] + bv.x;
            o0.y = acc[mt][nt][1] + bv.y;
            o1.x = acc[mt][nt][2] + bv.x;
            o1.y = acc[mt][nt][3] + bv.y;
            *(float2*)(C + (size_t)rg * Nn + cg) = o0;
            *(float2*)(C + (size_t)(rg + 8) * Nn + cg) = o1;
        }
    }
}

// ---------------- tensor-core persistent LSTM recurrence ----------------
// Block-cooperative h loads (race-free, R10 structure) + flag barrier (gbar2)
// + fused y hi/lo epilogue. CTA owns 8 hidden units -> 32 gate rows.
__global__ void __launch_bounds__(512, 1) lstm_rec_tc(
    const float* __restrict__ xg, const float* __restrict__ Whh,
    const float* __restrict__ h0, const float* __restrict__ c0,
    __nv_bfloat16* __restrict__ yhi, __nv_bfloat16* __restrict__ ylo,
    float* __restrict__ hT, float* __restrict__ cT)
{
    extern __shared__ char smem[];
    const uint32_t sb = smem_u32(smem);
    float* sres = (float*)(smem + SM_RES);
    const int tid  = threadIdx.x;
    const int wid  = tid >> 5;
    const int lane = tid & 31;
    const int cta  = blockIdx.x;

    const unsigned e0 = *((volatile unsigned*)&g_epoch);

    // ---- prologue: convert this CTA's 32 W_hh rows to split-bf16 in smem ----
    for (int i = tid; i < 32 * 256; i += 512) {
        int r  = i >> 8;
        int c4 = i & 255;
        int gr = (r >> 3) * H + cta * 8 + (r & 7);
        float4 v = *(const float4*)(Whh + (size_t)gr * H + c4 * 4);
        int e  = c4 * 4;
        int kc = e >> 7;
        uint32_t bo = (uint32_t)((e & 127) * 2);
        uint32_t off = (uint32_t)(kc * 8192 + r * 256) + (bo ^ (uint32_t)((r & 7) << 4));
        __nv_bfloat16 hx = __float2bfloat16(v.x), hy = __float2bfloat16(v.y);
        __nv_bfloat16 hz = __float2bfloat16(v.z), hw = __float2bfloat16(v.w);
        *(__nv_bfloat162*)(smem + SM_W + off)     = __nv_bfloat162(hx, hy);
        *(__nv_bfloat162*)(smem + SM_W + off + 4) = __nv_bfloat162(hz, hw);
        *(__nv_bfloat162*)(smem + SM_W + 65536 + off) =
            __nv_bfloat162(__float2bfloat16(v.x - __bfloat162float(hx)),
                           __float2bfloat16(v.y - __bfloat162float(hy)));
        *(__nv_bfloat162*)(smem + SM_W + 65536 + off + 4) =
            __nv_bfloat162(__float2bfloat16(v.z - __bfloat162float(hz)),
                           __float2bfloat16(v.w - __bfloat162float(hw)));
    }

    // ---- init: one (b, j) per thread ----
    const int eb = tid >> 3;
    const int ej = tid & 7;
    const int ejg = cta * 8 + ej;
    float creg;
    {
        float hv = h0[eb * H + ejg];
        __nv_bfloat16 hh = __float2bfloat16(hv);
        g_hb16[0][0][eb * H + ejg] = hh;
        g_hb16[0][1][eb * H + ejg] = __float2bfloat16(hv - __bfloat162float(hh));
        creg = c0[eb * H + ejg];
    }
    gbar2(e0 + 1);

    const int half = wid >> 3;
    const int wq   = wid & 7;
    const int wm = (wq >> 1) * 16;
    const int wn = (wq & 1) * 16;
    const int a_row = lane & 15;
    const int a_csel = ((lane >> 4) & 1) << 4;
    const int b_row = (lane & 7) + (((lane >> 4) & 1) << 3);
    const int b_csel = ((lane >> 3) & 1) << 4;

    for (int t = 0; t < T; ++t) {
        const __nv_bfloat16* hsrc0 = &g_hb16[t & 1][0][0];
        const __nv_bfloat16* hsrc1 = &g_hb16[t & 1][1][0];
        __nv_bfloat16* hdst0 = &g_hb16[(t + 1) & 1][0][0];
        __nv_bfloat16* hdst1 = &g_hb16[(t + 1) & 1][1][0];

        float xgv[4];
        {
            const float* xp = xg + ((size_t)(eb * T + t)) * G + ejg;
#pragma unroll
            for (int q = 0; q < 4; ++q) xgv[q] = __ldg(xp + q * H);
        }

        auto load_h = [&](int kc, int buf) {
            const uint32_t base = sb + SM_Hb + buf * 32768;
#pragma unroll
            for (int p = 0; p < 4; ++p) {
                int idx = tid + p * 512;
                int comp = idx >> 10;
                int ri = idx & 1023;
                int row = ri >> 4;
                int c16 = (ri & 15) << 4;
                const char* gp = (const char*)(comp ? hsrc1 : hsrc0) + kc * 256;
                cp_async16(base + comp * 16384 + row * 256 + (c16 ^ ((row & 7) << 4)),
                           gp + (size_t)row * 2048 + c16);
            }
            cp_commit();
        };

        float acc[2][4];
#pragma unroll
        for (int s = 0; s < 2; ++s)
#pragma unroll
            for (int k = 0; k < 4; ++k) acc[s][k] = 0.f;

        load_h(0, 0);
        for (int kc = 0; kc < 8; ++kc) {
            const int buf = kc & 1;
            if (kc + 1 < 8) { load_h(kc + 1, buf ^ 1); cp_wait<1>(); }
            else            { cp_wait<0>(); }
            __syncthreads();

            const uint32_t hHi = sb + SM_Hb + buf * 32768;
            const uint32_t hLo = hHi + 16384;
            const uint32_t wHi = sb + SM_W + kc * 8192;
            const uint32_t wLo = wHi + 65536;

#pragma unroll
            for (int ks4 = 0; ks4 < 4; ++ks4) {
                const int ks = half * 4 + ks4;
                const int acol = ks * 32 + a_csel;
                const int bcol = ks * 32 + b_csel;
                uint32_t ah[4], al[4], bh[4], bl[4];
                int arow = wm + a_row;
                uint32_t aoff = arow * 256 + (acol ^ ((arow & 7) << 4));
                ldsm4(ah, hHi + aoff);
                ldsm4(al, hLo + aoff);
                int brow = wn + b_row;
                uint32_t boff = brow * 256 + (bcol ^ ((brow & 7) << 4));
                ldsm4(bh, wHi + boff);
                ldsm4(bl, wLo + boff);
#pragma unroll
                for (int s = 0; s < 2; ++s) {
                    mma16816(acc[s], ah, &bh[s * 2]);
                    mma16816(acc[s], ah, &bl[s * 2]);
                    mma16816(acc[s], al, &bh[s * 2]);
                }
            }
            __syncthreads();
        }

        // stage partial accumulators to smem: sres[half][row][40]
        {
            int r0 = wm + (lane >> 2);
            int cb = wn + (lane & 3) * 2;
            float* rp = sres + half * 2560;
#pragma unroll
            for (int s = 0; s < 2; ++s) {
                *(float2*)&rp[r0 * 40 + cb + s * 8]       = make_float2(acc[s][0], acc[s][1]);
                *(float2*)&rp[(r0 + 8) * 40 + cb + s * 8] = make_float2(acc[s][2], acc[s][3]);
            }
        }
        __syncthreads();

        // epilogue: reduce halves + activations + state update + fused y hi/lo write
        {
            float iv = sres[eb * 40 + ej]      + sres[2560 + eb * 40 + ej]      + xgv[0];
            float fv = sres[eb * 40 + 8 + ej]  + sres[2560 + eb * 40 + 8 + ej]  + xgv[1];
            float gv = sres[eb * 40 + 16 + ej] + sres[2560 + eb * 40 + 16 + ej] + xgv[2];
            float ov = sres[eb * 40 + 24 + ej] + sres[2560 + eb * 40 + 24 + ej] + xgv[3];
            float ig = 1.f / (1.f + expf(-iv));
            float fg = 1.f / (1.f + expf(-fv));
            float gg = tanhf(gv);
            float og = 1.f / (1.f + expf(-ov));
            float cv = fg * creg + ig * gg;
            creg = cv;
            float hv = og * tanhf(cv);
            __nv_bfloat16 hh = __float2bfloat16(hv);
            __nv_bfloat16 hl = __float2bfloat16(hv - __bfloat162float(hh));
            hdst0[eb * H + ejg] = hh;
            hdst1[eb * H + ejg] = hl;
            size_t yoff = ((size_t)(eb * T + t)) * H + ejg;
            yhi[yoff] = hh;
            ylo[yoff] = hl;
            if (t == T - 1) { hT[eb * H + ejg] = hv; cT[eb * H + ejg] = cv; }
        }
        gbar2(e0 + 2 + t);
    }
}

// ---------------- launch ----------------
extern "C" void kernel_launch(void* const* d_in, const int* in_sizes, int n_in,
                              void* d_out, int out_size) {
    const float* x    = (const float*)d_in[0];
    const float* h0   = (const float*)d_in[1];
    const float* c0   = (const float*)d_in[2];
    const float* Wih0 = (const float*)d_in[3];
    const float* Whh0 = (const float*)d_in[4];
    const float* b0   = (const float*)d_in[5];
    const float* Wih1 = (const float*)d_in[6];
    const float* Whh1 = (const float*)d_in[7];
    const float* b1   = (const float*)d_in[8];
    const float* Wout = (const float*)d_in[9];
    const float* bout = (const float*)d_in[10];

    float* out     = (float*)d_out;
    float* out_act = out;
    float* out_h   = out + (size_t)M * V;
    float* out_c   = out_h + 2 * B * H;

    float *xg;
    __nv_bfloat16 *ahi, *alo, *whi, *wlo;
    cudaGetSymbolAddress((void**)&xg, g_xg);
    cudaGetSymbolAddress((void**)&ahi, g_act_hi);
    cudaGetSymbolAddress((void**)&alo, g_act_lo);
    cudaGetSymbolAddress((void**)&whi, g_w_hi);
    cudaGetSymbolAddress((void**)&wlo, g_w_lo);

    cudaFuncSetAttribute(gemm_mma, cudaFuncAttributeMaxDynamicSharedMemorySize, (int)SMEM_GM);
    cudaFuncSetAttribute(lstm_rec_tc, cudaFuncAttributeMaxDynamicSharedMemorySize, (int)SMEM_TC);

    // ---- Layer 0 input GEMM: xg = x @ Wih0^T + b0  (K=128) ----
    split_bf16<<<(M * V / 4 + 255) / 256, 256>>>(x, ahi, alo, M * V / 4);
    split_bf16<<<(G * V / 4 + 255) / 256, 256>>>(Wih0, whi, wlo, G * V / 4);
    gemm_mma<<<dim3(G / GM_BN, M / GM_BM), 256, SMEM_GM>>>(ahi, alo, whi, wlo, b0, xg, G, V);
    // ---- Layer 0 recurrence: writes y0 directly as bf16 hi/lo into act buffers ----
    lstm_rec_tc<<<NCTA, 512, SMEM_TC>>>(xg, Whh0, h0, c0, ahi, alo, out_h, out_c);
    // ---- Layer 1 input GEMM: xg = y0 @ Wih1^T + b1  (K=1024) ----
    split_bf16<<<(G * H / 4 + 255) / 256, 256>>>(Wih1, whi, wlo, G * H / 4);
    gemm_mma<<<dim3(G / GM_BN, M / GM_BM), 256, SMEM_GM>>>(ahi, alo, whi, wlo, b1, xg, G, H);
    // ---- Layer 1 recurrence: writes y1 into act buffers (y0 already consumed) ----
    lstm_rec_tc<<<NCTA, 512, SMEM_TC>>>(xg, Whh1, h0 + B * H, c0 + B * H, ahi, alo,
                                        out_h + B * H, out_c + B * H);
    // ---- Head: act = y1 @ Wout^T + b_out  (N=128, K=1024) ----
    split_bf16<<<(V * H / 4 + 255) / 256, 256>>>(Wout, whi, wlo, V * H / 4);
    gemm_mma<<<dim3(V / GM_BN, M / GM_BM), 256, SMEM_GM>>>(ahi, alo, whi, wlo, bout, out_act, V, H);
}

// round 14
// speedup vs baseline: 1.1574x; 1.1574x over previous
#include <cuda_runtime.h>
#include <cuda_bf16.h>
#include <cuda_fp16.h>
#include <cstdint>

#define B 64
#define T 256
#define V 128
#define H 1024
#define G 4096              // 4*H
#define M (B*T)             // 16384
#define NCTA 128

// ---------------- feed-forward mma GEMM tile config (BM64xBN128, 2 CTAs/SM) ----------------
#define GM_BM 64
#define GM_BN 128
#define GM_BK 64
#define GM_A_BYTES (64 * 128)
#define GM_B_BYTES (128 * 128)
#define GM_STAGE (2 * GM_A_BYTES + 2 * GM_B_BYTES)   // 48KB
#define SMEM_GM (2 * GM_STAGE)                       // 96KB -> 2 CTAs/SM

// ---------------- recurrence smem layout (bytes) ----------------
// W:  [hi|lo] x [8 kc][32 rows][256B]  -> 128 KB  (fp16; lo pre-scaled by 2048)
// H:  [2 buf][64 rows][256B]           ->  32 KB  (fp16 single)
// RES:[2 half][64][40] fp32            ->  20 KB
#define SM_W   0
#define SM_WLO 65536
#define SM_Hb  131072
#define SM_RES 163840
#define SMEM_TC (SM_RES + 2 * 64 * 40 * 4)   // 184320

// ---------------- scratch (static device arrays; no cudaMalloc) ----------------
__device__ float g_xg[(size_t)M * G];
__device__ __align__(16) __nv_bfloat16 g_act_hi[(size_t)M * H];
__device__ __align__(16) __nv_bfloat16 g_act_lo[(size_t)M * H];
__device__ __align__(16) __nv_bfloat16 g_w_hi[(size_t)G * H];
__device__ __align__(16) __nv_bfloat16 g_w_lo[(size_t)G * H];
__device__ __align__(16) __half g_h16[2][B * H];   // fp16 hidden state, double buffered
__device__ unsigned g_count;
__device__ unsigned g_epoch;

// ---------------- PTX helpers ----------------
__device__ __forceinline__ uint32_t smem_u32(const void* p) {
    uint32_t a;
    asm("{ .reg .u64 t; cvta.to.shared.u64 t, %1; cvt.u32.u64 %0, t; }" : "=r"(a) : "l"(p));
    return a;
}
__device__ __forceinline__ void cp_async16(uint32_t saddr, const void* gaddr) {
    asm volatile("cp.async.cg.shared.global [%0], [%1], 16;" :: "r"(saddr), "l"(gaddr) : "memory");
}
__device__ __forceinline__ void cp_commit() {
    asm volatile("cp.async.commit_group;" ::: "memory");
}
template <int N>
__device__ __forceinline__ void cp_wait() {
    asm volatile("cp.async.wait_group %0;" :: "n"(N) : "memory");
}
__device__ __forceinline__ void ldsm4(uint32_t* r, uint32_t addr) {
    asm volatile("ldmatrix.sync.aligned.m8n8.x4.shared.b16 {%0,%1,%2,%3}, [%4];"
        : "=r"(r[0]), "=r"(r[1]), "=r"(r[2]), "=r"(r[3]) : "r"(addr));
}
// bf16 mma (feed-forward GEMM)
__device__ __forceinline__ void mma16816(float* d, const uint32_t* a, const uint32_t* b) {
    asm volatile("mma.sync.aligned.m16n8k16.row.col.f32.bf16.bf16.f32 "
        "{%0,%1,%2,%3}, {%4,%5,%6,%7}, {%8,%9}, {%0,%1,%2,%3};"
        : "+f"(d[0]), "+f"(d[1]), "+f"(d[2]), "+f"(d[3])
        : "r"(a[0]), "r"(a[1]), "r"(a[2]), "r"(a[3]), "r"(b[0]), "r"(b[1]));
}
// fp16 mma (recurrence)
__device__ __forceinline__ void mma16816h(float* d, const uint32_t* a, const uint32_t* b) {
    asm volatile("mma.sync.aligned.m16n8k16.row.col.f32.f16.f16.f32 "
        "{%0,%1,%2,%3}, {%4,%5,%6,%7}, {%8,%9}, {%0,%1,%2,%3};"
        : "+f"(d[0]), "+f"(d[1]), "+f"(d[2]), "+f"(d[3])
        : "r"(a[0]), "r"(a[1]), "r"(a[2]), "r"(a[3]), "r"(b[0]), "r"(b[1]));
}

// ---------------- software grid barrier (R10 atomic version, single-thread poll) ----------------
__device__ __forceinline__ void gbar(unsigned target) {
    __threadfence();
    __syncthreads();
    if (threadIdx.x == 0) {
        unsigned prev = atomicAdd(&g_count, 1u);
        if (prev == NCTA - 1) {
            g_count = 0u;
            __threadfence();
            *((volatile unsigned*)&g_epoch) = target;
        } else {
            while (*((volatile unsigned*)&g_epoch) != target) { __nanosleep(32); }
            __threadfence();
        }
    }
    __syncthreads();
}

// ---------------- fp32 -> bf16 hi/lo split (elementwise) ----------------
__global__ void __launch_bounds__(256) split_bf16(
    const float* __restrict__ in, __nv_bfloat16* __restrict__ hi,
    __nv_bfloat16* __restrict__ lo, int n4)
{
    int i = blockIdx.x * 256 + threadIdx.x;
    if (i >= n4) return;
    float4 v = ((const float4*)in)[i];
    __nv_bfloat16 h0 = __float2bfloat16(v.x);
    __nv_bfloat16 h1 = __float2bfloat16(v.y);
    __nv_bfloat16 h2 = __float2bfloat16(v.z);
    __nv_bfloat16 h3 = __float2bfloat16(v.w);
    __nv_bfloat16 l0 = __float2bfloat16(v.x - __bfloat162float(h0));
    __nv_bfloat16 l1 = __float2bfloat16(v.y - __bfloat162float(h1));
    __nv_bfloat16 l2 = __float2bfloat16(v.z - __bfloat162float(h2));
    __nv_bfloat16 l3 = __float2bfloat16(v.w - __bfloat162float(h3));
    ((__nv_bfloat162*)hi)[2 * i]     = __nv_bfloat162(h0, h1);
    ((__nv_bfloat162*)hi)[2 * i + 1] = __nv_bfloat162(h2, h3);
    ((__nv_bfloat162*)lo)[2 * i]     = __nv_bfloat162(l0, l1);
    ((__nv_bfloat162*)lo)[2 * i + 1] = __nv_bfloat162(l2, l3);
}

// ---------------- split-bf16 tensor GEMM: BM=64, BN=128, 2-stage, 2 CTAs/SM (unchanged) ----------------
__global__ void __launch_bounds__(256, 2) gemm_mma(
    const __nv_bfloat16* __restrict__ Ahi, const __nv_bfloat16* __restrict__ Alo,
    const __nv_bfloat16* __restrict__ Bhi, const __nv_bfloat16* __restrict__ Blo,
    const float* __restrict__ bias, float* __restrict__ C, int Nn, int Kk)
{
    extern __shared__ char smem[];
    const uint32_t sb = smem_u32(smem);
    const int tid  = threadIdx.x;
    const int wid  = tid >> 5;
    const int lane = tid & 31;
    const int m0 = blockIdx.y * GM_BM;
    const int n0 = blockIdx.x * GM_BN;
    const int wm = (wid >> 2) * 32;
    const int wn = (wid & 3) * 32;

    const char* srcs[4];
    srcs[0] = (const char*)(Ahi + (size_t)m0 * Kk);
    srcs[1] = (const char*)(Alo + (size_t)m0 * Kk);
    srcs[2] = (const char*)(Bhi + (size_t)n0 * Kk);
    srcs[3] = (const char*)(Blo + (size_t)n0 * Kk);
    const size_t rstride = (size_t)Kk * 2;
    const int nk = Kk / GM_BK;

    auto load_chunk = [&](int kt, int buf) {
        const uint32_t base = sb + buf * GM_STAGE;
#pragma unroll
        for (int tgt = 0; tgt < 2; ++tgt) {
            const char* gp = srcs[tgt] + (size_t)kt * 128;
            const uint32_t tb = base + tgt * GM_A_BYTES;
#pragma unroll
            for (int p = 0; p < 2; ++p) {
                int idx = tid + p * 256;
                int row = idx >> 3;
                int c16 = (idx & 7) << 4;
                cp_async16(tb + row * 128 + (c16 ^ ((row & 7) << 4)),
                           gp + (size_t)row * rstride + c16);
            }
        }
#pragma unroll
        for (int tgt = 2; tgt < 4; ++tgt) {
            const char* gp = srcs[tgt] + (size_t)kt * 128;
            const uint32_t tb = base + 2 * GM_A_BYTES + (tgt - 2) * GM_B_BYTES;
#pragma unroll
            for (int p = 0; p < 4; ++p) {
                int idx = tid + p * 256;
                int row = idx >> 3;
                int c16 = (idx & 7) << 4;
                cp_async16(tb + row * 128 + (c16 ^ ((row & 7) << 4)),
                           gp + (size_t)row * rstride + c16);
            }
        }
        cp_commit();
    };

    float acc[2][4][4];
#pragma unroll
    for (int i = 0; i < 2; ++i)
#pragma unroll
        for (int j = 0; j < 4; ++j)
#pragma unroll
            for (int k = 0; k < 4; ++k) acc[i][j][k] = 0.f;

    load_chunk(0, 0);

    const int a_row = lane & 15;
    const int a_csel = ((lane >> 4) & 1) << 4;
    const int b_row = (lane & 7) + (((lane >> 4) & 1) << 3);
    const int b_csel = ((lane >> 3) & 1) << 4;

    for (int kt = 0; kt < nk; ++kt) {
        const int buf = kt & 1;
        if (kt + 1 < nk) { load_chunk(kt + 1, buf ^ 1); cp_wait<1>(); }
        else             { cp_wait<0>(); }
        __syncthreads();

        const uint32_t base = sb + buf * GM_STAGE;
        const uint32_t aHiB = base;
        const uint32_t aLoB = base + GM_A_BYTES;
        const uint32_t bHiB = base + 2 * GM_A_BYTES;
        const uint32_t bLoB = bHiB + GM_B_BYTES;

#pragma unroll
        for (int ks = 0; ks < 4; ++ks) {
            const int acol = ks * 32 + a_csel;
            const int bcol = ks * 32 + b_csel;
            uint32_t ahi[2][4], alo[2][4];
#pragma unroll
            for (int mt = 0; mt < 2; ++mt) {
                int row = wm + mt * 16 + a_row;
                uint32_t off = row * 128 + (acol ^ ((row & 7) << 4));
                ldsm4(ahi[mt], aHiB + off);
                ldsm4(alo[mt], aLoB + off);
            }
            uint32_t bhi[2][4], blo[2][4];
#pragma unroll
            for (int np = 0; np < 2; ++np) {
                int row = wn + np * 16 + b_row;
                uint32_t off = row * 128 + (bcol ^ ((row & 7) << 4));
                ldsm4(bhi[np], bHiB + off);
                ldsm4(blo[np], bLoB + off);
            }
#pragma unroll
            for (int mt = 0; mt < 2; ++mt)
#pragma unroll
                for (int np = 0; np < 2; ++np)
#pragma unroll
                    for (int s = 0; s < 2; ++s) {
                        int nt = np * 2 + s;
                        mma16816(acc[mt][nt], ahi[mt], &bhi[np][s * 2]);
                        mma16816(acc[mt][nt], ahi[mt], &blo[np][s * 2]);
                        mma16816(acc[mt][nt], alo[mt], &bhi[np][s * 2]);
                    }
        }
        __syncthreads();
    }

#pragma unroll
    for (int mt = 0; mt < 2; ++mt) {
        const int rg = m0 + wm + mt * 16 + (lane >> 2);
#pragma unroll
        for (int nt = 0; nt < 4; ++nt) {
            const int cg = n0 + wn + nt * 8 + (lane & 3) * 2;
            const float2 bv = *(const float2*)(bias + cg);
            float2 o0, o1;
            o0.x = acc[mt][nt][0] + bv.x;
            o0.y = acc[mt][nt][1] + bv.y;
            o1.x = acc[mt][nt][2] + bv.x;
            o1.y = acc[mt][nt][3] + bv.y;
            *(float2*)(C + (size_t)rg * Nn + cg) = o0;
            *(float2*)(C + (size_t)(rg + 8) * Nn + cg) = o1;
        }
    }
}

// ---------------- tensor-core persistent LSTM recurrence (one-sided fp16 split) ----------------
// h: single fp16 stream (2x less smem-pipe work + L2 traffic).
// W: fp16 hi + fp16 (residual*2048); separate fp32 accumulators, epilogue combines
// acc_hi + acc_lo/2048 (W error ~2^-22; total error = h quantization ~2^-11).
__global__ void __launch_bounds__(512, 1) lstm_rec_tc(
    const float* __restrict__ xg, const float* __restrict__ Whh,
    const float* __restrict__ h0, const float* __restrict__ c0,
    __nv_bfloat16* __restrict__ yhi, __nv_bfloat16* __restrict__ ylo,
    float* __restrict__ hT, float* __restrict__ cT)
{
    extern __shared__ char smem[];
    const uint32_t sb = smem_u32(smem);
    float* sres = (float*)(smem + SM_RES);
    const int tid  = threadIdx.x;
    const int wid  = tid >> 5;
    const int lane = tid & 31;
    const int cta  = blockIdx.x;

    const unsigned e0 = *((volatile unsigned*)&g_epoch);

    // ---- prologue: convert this CTA's 32 W_hh rows to fp16 hi + scaled-lo in smem ----
    for (int i = tid; i < 32 * 256; i += 512) {
        int r  = i >> 8;
        int c4 = i & 255;
        int gr = (r >> 3) * H + cta * 8 + (r & 7);
        float4 v = *(const float4*)(Whh + (size_t)gr * H + c4 * 4);
        int e  = c4 * 4;
        int kc = e >> 7;
        uint32_t bo = (uint32_t)((e & 127) * 2);
        uint32_t off = (uint32_t)(kc * 8192 + r * 256) + (bo ^ (uint32_t)((r & 7) << 4));
        __half hx = __float2half_rn(v.x), hy = __float2half_rn(v.y);
        __half hz = __float2half_rn(v.z), hw = __float2half_rn(v.w);
        *(__half2*)(smem + SM_W + off)     = __halves2half2(hx, hy);
        *(__half2*)(smem + SM_W + off + 4) = __halves2half2(hz, hw);
        *(__half2*)(smem + SM_WLO + off) = __halves2half2(
            __float2half_rn((v.x - __half2float(hx)) * 2048.0f),
            __float2half_rn((v.y - __half2float(hy)) * 2048.0f));
        *(__half2*)(smem + SM_WLO + off + 4) = __halves2half2(
            __float2half_rn((v.z - __half2float(hz)) * 2048.0f),
            __float2half_rn((v.w - __half2float(hw)) * 2048.0f));
    }

    // ---- init: one (b, j) per thread ----
    const int eb = tid >> 3;
    const int ej = tid & 7;
    const int ejg = cta * 8 + ej;
    float creg;
    {
        float hv = h0[eb * H + ejg];
        g_h16[0][eb * H + ejg] = __float2half_rn(hv);
        creg = c0[eb * H + ejg];
    }
    gbar(e0 + 1);

    const int half = wid >> 3;
    const int wq   = wid & 7;
    const int wm = (wq >> 1) * 16;
    const int wn = (wq & 1) * 16;
    const int a_row = lane & 15;
    const int a_csel = ((lane >> 4) & 1) << 4;
    const int b_row = (lane & 7) + (((lane >> 4) & 1) << 3);
    const int b_csel = ((lane >> 3) & 1) << 4;

    for (int t = 0; t < T; ++t) {
        const __half* hsrc = &g_h16[t & 1][0];
        __half* hdst = &g_h16[(t + 1) & 1][0];

        float xgv[4];
        {
            const float* xp = xg + ((size_t)(eb * T + t)) * G + ejg;
#pragma unroll
            for (int q = 0; q < 4; ++q) xgv[q] = __ldg(xp + q * H);
        }

        // h chunk kc: 64 rows x 128 fp16 = 16KB; 1024 cp.async16 = 2 per thread
        auto load_h = [&](int kc, int buf) {
            const uint32_t base = sb + SM_Hb + buf * 16384;
            const char* gp = (const char*)hsrc + kc * 256;
#pragma unroll
            for (int p = 0; p < 2; ++p) {
                int idx = tid + p * 512;          // 0..1023
                int row = idx >> 4;               // 0..63
                int c16 = (idx & 15) << 4;        // 0..240
                cp_async16(base + row * 256 + (c16 ^ ((row & 7) << 4)),
                           gp + (size_t)row * 2048 + c16);
            }
            cp_commit();
        };

        float accH[2][4], accL[2][4];
#pragma unroll
        for (int s = 0; s < 2; ++s)
#pragma unroll
            for (int k = 0; k < 4; ++k) { accH[s][k] = 0.f; accL[s][k] = 0.f; }

        load_h(0, 0);
        for (int kc = 0; kc < 8; ++kc) {
            const int buf = kc & 1;
            if (kc + 1 < 8) { load_h(kc + 1, buf ^ 1); cp_wait<1>(); }
            else            { cp_wait<0>(); }
            __syncthreads();

            const uint32_t hB  = sb + SM_Hb + buf * 16384;
            const uint32_t wHi = sb + SM_W + kc * 8192;
            const uint32_t wLo = sb + SM_WLO + kc * 8192;

#pragma unroll
            for (int ks4 = 0; ks4 < 4; ++ks4) {
                const int ks = half * 4 + ks4;
                const int acol = ks * 32 + a_csel;
                const int bcol = ks * 32 + b_csel;
                uint32_t ah[4], bh[4], bl[4];
                int arow = wm + a_row;
                uint32_t aoff = arow * 256 + (acol ^ ((arow & 7) << 4));
                ldsm4(ah, hB + aoff);
                int brow = wn + b_row;
                uint32_t boff = brow * 256 + (bcol ^ ((brow & 7) << 4));
                ldsm4(bh, wHi + boff);
                ldsm4(bl, wLo + boff);
#pragma unroll
                for (int s = 0; s < 2; ++s) {
                    mma16816h(accH[s], ah, &bh[s * 2]);
                    mma16816h(accL[s], ah, &bl[s * 2]);
                }
            }
            __syncthreads();
        }

        // combine hi + lo/2048, stage partials: sres[half][row][40]
        {
            int r0 = wm + (lane >> 2);
            int cb = wn + (lane & 3) * 2;
            float* rp = sres + half * 2560;
            const float inv = 4.8828125e-4f;   // 1/2048
#pragma unroll
            for (int s = 0; s < 2; ++s) {
                *(float2*)&rp[r0 * 40 + cb + s * 8] =
                    make_float2(accH[s][0] + accL[s][0] * inv, accH[s][1] + accL[s][1] * inv);
                *(float2*)&rp[(r0 + 8) * 40 + cb + s * 8] =
                    make_float2(accH[s][2] + accL[s][2] * inv, accH[s][3] + accL[s][3] * inv);
            }
        }
        __syncthreads();

        // epilogue: reduce halves + activations + state update + writes
        {
            float iv = sres[eb * 40 + ej]      + sres[2560 + eb * 40 + ej]      + xgv[0];
            float fv = sres[eb * 40 + 8 + ej]  + sres[2560 + eb * 40 + 8 + ej]  + xgv[1];
            float gv = sres[eb * 40 + 16 + ej] + sres[2560 + eb * 40 + 16 + ej] + xgv[2];
            float ov = sres[eb * 40 + 24 + ej] + sres[2560 + eb * 40 + 24 + ej] + xgv[3];
            float ig = 1.f / (1.f + expf(-iv));
            float fg = 1.f / (1.f + expf(-fv));
            float gg = tanhf(gv);
            float og = 1.f / (1.f + expf(-ov));
            float cv = fg * creg + ig * gg;
            creg = cv;
            float hv = og * tanhf(cv);
            hdst[eb * H + ejg] = __float2half_rn(hv);
            __nv_bfloat16 hh = __float2bfloat16(hv);
            size_t yoff = ((size_t)(eb * T + t)) * H + ejg;
            yhi[yoff] = hh;
            ylo[yoff] = __float2bfloat16(hv - __bfloat162float(hh));
            if (t == T - 1) { hT[eb * H + ejg] = hv; cT[eb * H + ejg] = cv; }
        }
        gbar(e0 + 2 + t);
    }
}

// ---------------- launch ----------------
extern "C" void kernel_launch(void* const* d_in, const int* in_sizes, int n_in,
                              void* d_out, int out_size) {
    const float* x    = (const float*)d_in[0];
    const float* h0   = (const float*)d_in[1];
    const float* c0   = (const float*)d_in[2];
    const float* Wih0 = (const float*)d_in[3];
    const float* Whh0 = (const float*)d_in[4];
    const float* b0   = (const float*)d_in[5];
    const float* Wih1 = (const float*)d_in[6];
    const float* Whh1 = (const float*)d_in[7];
    const float* b1   = (const float*)d_in[8];
    const float* Wout = (const float*)d_in[9];
    const float* bout = (const float*)d_in[10];

    float* out     = (float*)d_out;
    float* out_act = out;
    float* out_h   = out + (size_t)M * V;
    float* out_c   = out_h + 2 * B * H;

    float *xg;
    __nv_bfloat16 *ahi, *alo, *whi, *wlo;
    cudaGetSymbolAddress((void**)&xg, g_xg);
    cudaGetSymbolAddress((void**)&ahi, g_act_hi);
    cudaGetSymbolAddress((void**)&alo, g_act_lo);
    cudaGetSymbolAddress((void**)&whi, g_w_hi);
    cudaGetSymbolAddress((void**)&wlo, g_w_lo);

    cudaFuncSetAttribute(gemm_mma, cudaFuncAttributeMaxDynamicSharedMemorySize, (int)SMEM_GM);
    cudaFuncSetAttribute(lstm_rec_tc, cudaFuncAttributeMaxDynamicSharedMemorySize, (int)SMEM_TC);

    // ---- Layer 0 input GEMM: xg = x @ Wih0^T + b0  (K=128) ----
    split_bf16<<<(M * V / 4 + 255) / 256, 256>>>(x, ahi, alo, M * V / 4);
    split_bf16<<<(G * V / 4 + 255) / 256, 256>>>(Wih0, whi, wlo, G * V / 4);
    gemm_mma<<<dim3(G / GM_BN, M / GM_BM), 256, SMEM_GM>>>(ahi, alo, whi, wlo, b0, xg, G, V);
    // ---- Layer 0 recurrence: writes y0 as bf16 hi/lo into act buffers ----
    lstm_rec_tc<<<NCTA, 512, SMEM_TC>>>(xg, Whh0, h0, c0, ahi, alo, out_h, out_c);
    // ---- Layer 1 input GEMM: xg = y0 @ Wih1^T + b1  (K=1024) ----
    split_bf16<<<(G * H / 4 + 255) / 256, 256>>>(Wih1, whi, wlo, G * H / 4);
    gemm_mma<<<dim3(G / GM_BN, M / GM_BM), 256, SMEM_GM>>>(ahi, alo, whi, wlo, b1, xg, G, H);
    // ---- Layer 1 recurrence ----
    lstm_rec_tc<<<NCTA, 512, SMEM_TC>>>(xg, Whh1, h0 + B * H, c0 + B * H, ahi, alo,
                                        out_h + B * H, out_c + B * H);
    // ---- Head: act = y1 @ Wout^T + b_out  (N=128, K=1024) ----
    split_bf16<<<(V * H / 4 + 255) / 256, 256>>>(Wout, whi, wlo, V * H / 4);
    gemm_mma<<<dim3(V / GM_BN, M / GM_BM), 256, SMEM_GM>>>(ahi, alo, whi, wlo, bout, out_act, V, H);
}

// round 15
// speedup vs baseline: 1.3175x; 1.1383x over previous
#include <cuda_runtime.h>
#include <cuda_bf16.h>
#include <cuda_fp16.h>
#include <cstdint>

#define B 64
#define T 256
#define V 128
#define H 1024
#define G 4096              // 4*H
#define M (B*T)             // 16384
#define NCTA 128

// ---------------- feed-forward mma GEMM tile config (BM64xBN128, 2 CTAs/SM) ----------------
#define GM_BM 64
#define GM_BN 128
#define GM_BK 64
#define GM_A_BYTES (64 * 128)
#define GM_B_BYTES (128 * 128)
#define GM_STAGE (2 * GM_A_BYTES + 2 * GM_B_BYTES)   // 48KB
#define SMEM_GM (2 * GM_STAGE)                       // 96KB -> 2 CTAs/SM

// ---------------- recurrence smem layout (bytes) ----------------
// W:  [8 kc][32 rows][256B] fp16 hi only     -> 64 KB
// H:  [3 buf][64 rows][256B] fp16            -> 48 KB
// RES:[2 half][64][40] fp32                  -> 20 KB
#define SM_W   0
#define SM_Hb  65536
#define SM_RES 114688
#define SMEM_TC (SM_RES + 2 * 64 * 40 * 4)   // 135168

// ---------------- scratch (static device arrays; no cudaMalloc) ----------------
__device__ float g_xg[(size_t)M * G];
__device__ __align__(16) __nv_bfloat16 g_act_hi[(size_t)M * H];
__device__ __align__(16) __nv_bfloat16 g_act_lo[(size_t)M * H];
__device__ __align__(16) __nv_bfloat16 g_w_hi[(size_t)G * H];
__device__ __align__(16) __nv_bfloat16 g_w_lo[(size_t)G * H];
__device__ __align__(16) __half g_h16[2][B * H];   // fp16 hidden state, double buffered
__device__ unsigned g_count;
__device__ unsigned g_epoch;

// ---------------- PTX helpers ----------------
__device__ __forceinline__ uint32_t smem_u32(const void* p) {
    uint32_t a;
    asm("{ .reg .u64 t; cvta.to.shared.u64 t, %1; cvt.u32.u64 %0, t; }" : "=r"(a) : "l"(p));
    return a;
}
__device__ __forceinline__ void cp_async16(uint32_t saddr, const void* gaddr) {
    asm volatile("cp.async.cg.shared.global [%0], [%1], 16;" :: "r"(saddr), "l"(gaddr) : "memory");
}
__device__ __forceinline__ void cp_commit() {
    asm volatile("cp.async.commit_group;" ::: "memory");
}
template <int N>
__device__ __forceinline__ void cp_wait() {
    asm volatile("cp.async.wait_group %0;" :: "n"(N) : "memory");
}
__device__ __forceinline__ void ldsm4(uint32_t* r, uint32_t addr) {
    asm volatile("ldmatrix.sync.aligned.m8n8.x4.shared.b16 {%0,%1,%2,%3}, [%4];"
        : "=r"(r[0]), "=r"(r[1]), "=r"(r[2]), "=r"(r[3]) : "r"(addr));
}
// bf16 mma (feed-forward GEMM)
__device__ __forceinline__ void mma16816(float* d, const uint32_t* a, const uint32_t* b) {
    asm volatile("mma.sync.aligned.m16n8k16.row.col.f32.bf16.bf16.f32 "
        "{%0,%1,%2,%3}, {%4,%5,%6,%7}, {%8,%9}, {%0,%1,%2,%3};"
        : "+f"(d[0]), "+f"(d[1]), "+f"(d[2]), "+f"(d[3])
        : "r"(a[0]), "r"(a[1]), "r"(a[2]), "r"(a[3]), "r"(b[0]), "r"(b[1]));
}
// fp16 mma (recurrence)
__device__ __forceinline__ void mma16816h(float* d, const uint32_t* a, const uint32_t* b) {
    asm volatile("mma.sync.aligned.m16n8k16.row.col.f32.f16.f16.f32 "
        "{%0,%1,%2,%3}, {%4,%5,%6,%7}, {%8,%9}, {%0,%1,%2,%3};"
        : "+f"(d[0]), "+f"(d[1]), "+f"(d[2]), "+f"(d[3])
        : "r"(a[0]), "r"(a[1]), "r"(a[2]), "r"(a[3]), "r"(b[0]), "r"(b[1]));
}

// ---------------- software grid barrier (atomic, single-thread poll) ----------------
__device__ __forceinline__ void gbar(unsigned target) {
    __threadfence();
    __syncthreads();
    if (threadIdx.x == 0) {
        unsigned prev = atomicAdd(&g_count, 1u);
        if (prev == NCTA - 1) {
            g_count = 0u;
            __threadfence();
            *((volatile unsigned*)&g_epoch) = target;
        } else {
            while (*((volatile unsigned*)&g_epoch) != target) { __nanosleep(32); }
            __threadfence();
        }
    }
    __syncthreads();
}

// ---------------- fp32 -> bf16 hi/lo split (elementwise) ----------------
__global__ void __launch_bounds__(256) split_bf16(
    const float* __restrict__ in, __nv_bfloat16* __restrict__ hi,
    __nv_bfloat16* __restrict__ lo, int n4)
{
    int i = blockIdx.x * 256 + threadIdx.x;
    if (i >= n4) return;
    float4 v = ((const float4*)in)[i];
    __nv_bfloat16 h0 = __float2bfloat16(v.x);
    __nv_bfloat16 h1 = __float2bfloat16(v.y);
    __nv_bfloat16 h2 = __float2bfloat16(v.z);
    __nv_bfloat16 h3 = __float2bfloat16(v.w);
    __nv_bfloat16 l0 = __float2bfloat16(v.x - __bfloat162float(h0));
    __nv_bfloat16 l1 = __float2bfloat16(v.y - __bfloat162float(h1));
    __nv_bfloat16 l2 = __float2bfloat16(v.z - __bfloat162float(h2));
    __nv_bfloat16 l3 = __float2bfloat16(v.w - __bfloat162float(h3));
    ((__nv_bfloat162*)hi)[2 * i]     = __nv_bfloat162(h0, h1);
    ((__nv_bfloat162*)hi)[2 * i + 1] = __nv_bfloat162(h2, h3);
    ((__nv_bfloat162*)lo)[2 * i]     = __nv_bfloat162(l0, l1);
    ((__nv_bfloat162*)lo)[2 * i + 1] = __nv_bfloat162(l2, l3);
}

// ---------------- split-bf16 tensor GEMM: BM=64, BN=128, 2-stage, 2 CTAs/SM (unchanged) ----------------
__global__ void __launch_bounds__(256, 2) gemm_mma(
    const __nv_bfloat16* __restrict__ Ahi, const __nv_bfloat16* __restrict__ Alo,
    const __nv_bfloat16* __restrict__ Bhi, const __nv_bfloat16* __restrict__ Blo,
    const float* __restrict__ bias, float* __restrict__ C, int Nn, int Kk)
{
    extern __shared__ char smem[];
    const uint32_t sb = smem_u32(smem);
    const int tid  = threadIdx.x;
    const int wid  = tid >> 5;
    const int lane = tid & 31;
    const int m0 = blockIdx.y * GM_BM;
    const int n0 = blockIdx.x * GM_BN;
    const int wm = (wid >> 2) * 32;
    const int wn = (wid & 3) * 32;

    const char* srcs[4];
    srcs[0] = (const char*)(Ahi + (size_t)m0 * Kk);
    srcs[1] = (const char*)(Alo + (size_t)m0 * Kk);
    srcs[2] = (const char*)(Bhi + (size_t)n0 * Kk);
    srcs[3] = (const char*)(Blo + (size_t)n0 * Kk);
    const size_t rstride = (size_t)Kk * 2;
    const int nk = Kk / GM_BK;

    auto load_chunk = [&](int kt, int buf) {
        const uint32_t base = sb + buf * GM_STAGE;
#pragma unroll
        for (int tgt = 0; tgt < 2; ++tgt) {
            const char* gp = srcs[tgt] + (size_t)kt * 128;
            const uint32_t tb = base + tgt * GM_A_BYTES;
#pragma unroll
            for (int p = 0; p < 2; ++p) {
                int idx = tid + p * 256;
                int row = idx >> 3;
                int c16 = (idx & 7) << 4;
                cp_async16(tb + row * 128 + (c16 ^ ((row & 7) << 4)),
                           gp + (size_t)row * rstride + c16);
            }
        }
#pragma unroll
        for (int tgt = 2; tgt < 4; ++tgt) {
            const char* gp = srcs[tgt] + (size_t)kt * 128;
            const uint32_t tb = base + 2 * GM_A_BYTES + (tgt - 2) * GM_B_BYTES;
#pragma unroll
            for (int p = 0; p < 4; ++p) {
                int idx = tid + p * 256;
                int row = idx >> 3;
                int c16 = (idx & 7) << 4;
                cp_async16(tb + row * 128 + (c16 ^ ((row & 7) << 4)),
                           gp + (size_t)row * rstride + c16);
            }
        }
        cp_commit();
    };

    float acc[2][4][4];
#pragma unroll
    for (int i = 0; i < 2; ++i)
#pragma unroll
        for (int j = 0; j < 4; ++j)
#pragma unroll
            for (int k = 0; k < 4; ++k) acc[i][j][k] = 0.f;

    load_chunk(0, 0);

    const int a_row = lane & 15;
    const int a_csel = ((lane >> 4) & 1) << 4;
    const int b_row = (lane & 7) + (((lane >> 4) & 1) << 3);
    const int b_csel = ((lane >> 3) & 1) << 4;

    for (int kt = 0; kt < nk; ++kt) {
        const int buf = kt & 1;
        if (kt + 1 < nk) { load_chunk(kt + 1, buf ^ 1); cp_wait<1>(); }
        else             { cp_wait<0>(); }
        __syncthreads();

        const uint32_t base = sb + buf * GM_STAGE;
        const uint32_t aHiB = base;
        const uint32_t aLoB = base + GM_A_BYTES;
        const uint32_t bHiB = base + 2 * GM_A_BYTES;
        const uint32_t bLoB = bHiB + GM_B_BYTES;

#pragma unroll
        for (int ks = 0; ks < 4; ++ks) {
            const int acol = ks * 32 + a_csel;
            const int bcol = ks * 32 + b_csel;
            uint32_t ahi[2][4], alo[2][4];
#pragma unroll
            for (int mt = 0; mt < 2; ++mt) {
                int row = wm + mt * 16 + a_row;
                uint32_t off = row * 128 + (acol ^ ((row & 7) << 4));
                ldsm4(ahi[mt], aHiB + off);
                ldsm4(alo[mt], aLoB + off);
            }
            uint32_t bhi[2][4], blo[2][4];
#pragma unroll
            for (int np = 0; np < 2; ++np) {
                int row = wn + np * 16 + b_row;
                uint32_t off = row * 128 + (bcol ^ ((row & 7) << 4));
                ldsm4(bhi[np], bHiB + off);
                ldsm4(blo[np], bLoB + off);
            }
#pragma unroll
            for (int mt = 0; mt < 2; ++mt)
#pragma unroll
                for (int np = 0; np < 2; ++np)
#pragma unroll
                    for (int s = 0; s < 2; ++s) {
                        int nt = np * 2 + s;
                        mma16816(acc[mt][nt], ahi[mt], &bhi[np][s * 2]);
                        mma16816(acc[mt][nt], ahi[mt], &blo[np][s * 2]);
                        mma16816(acc[mt][nt], alo[mt], &bhi[np][s * 2]);
                    }
        }
        __syncthreads();
    }

#pragma unroll
    for (int mt = 0; mt < 2; ++mt) {
        const int rg = m0 + wm + mt * 16 + (lane >> 2);
#pragma unroll
        for (int nt = 0; nt < 4; ++nt) {
            const int cg = n0 + wn + nt * 8 + (lane & 3) * 2;
            const float2 bv = *(const float2*)(bias + cg);
            float2 o0, o1;
            o0.x = acc[mt][nt][0] + bv.x;
            o0.y = acc[mt][nt][1] + bv.y;
            o1.x = acc[mt][nt][2] + bv.x;
            o1.y = acc[mt][nt][3] + bv.y;
            *(float2*)(C + (size_t)rg * Nn + cg) = o0;
            *(float2*)(C + (size_t)(rg + 8) * Nn + cg) = o1;
        }
    }
}

// ---------------- tensor-core persistent LSTM recurrence (fp16 W + fp16 h) ----------------
// W_hh and h both single fp16 (errors ~2^-11 each, average down through the
// 1024-wide gate sums). Triple-buffered h chunks -> ONE __syncthreads per chunk.
__global__ void __launch_bounds__(512, 1) lstm_rec_tc(
    const float* __restrict__ xg, const float* __restrict__ Whh,
    const float* __restrict__ h0, const float* __restrict__ c0,
    __nv_bfloat16* __restrict__ yhi, __nv_bfloat16* __restrict__ ylo,
    float* __restrict__ hT, float* __restrict__ cT)
{
    extern __shared__ char smem[];
    const uint32_t sb = smem_u32(smem);
    float* sres = (float*)(smem + SM_RES);
    const int tid  = threadIdx.x;
    const int wid  = tid >> 5;
    const int lane = tid & 31;
    const int cta  = blockIdx.x;

    const unsigned e0 = *((volatile unsigned*)&g_epoch);

    // ---- prologue: convert this CTA's 32 W_hh rows to fp16 in smem ----
    for (int i = tid; i < 32 * 256; i += 512) {
        int r  = i >> 8;
        int c4 = i & 255;
        int gr = (r >> 3) * H + cta * 8 + (r & 7);
        float4 v = *(const float4*)(Whh + (size_t)gr * H + c4 * 4);
        int e  = c4 * 4;
        int kc = e >> 7;
        uint32_t bo = (uint32_t)((e & 127) * 2);
        uint32_t off = (uint32_t)(kc * 8192 + r * 256) + (bo ^ (uint32_t)((r & 7) << 4));
        *(__half2*)(smem + SM_W + off) =
            __halves2half2(__float2half_rn(v.x), __float2half_rn(v.y));
        *(__half2*)(smem + SM_W + off + 4) =
            __halves2half2(__float2half_rn(v.z), __float2half_rn(v.w));
    }

    // ---- init: one (b, j) per thread ----
    const int eb = tid >> 3;
    const int ej = tid & 7;
    const int ejg = cta * 8 + ej;
    float creg;
    {
        float hv = h0[eb * H + ejg];
        g_h16[0][eb * H + ejg] = __float2half_rn(hv);
        creg = c0[eb * H + ejg];
    }
    gbar(e0 + 1);

    const int half = wid >> 3;
    const int wq   = wid & 7;
    const int wm = (wq >> 1) * 16;
    const int wn = (wq & 1) * 16;
    const int a_row = lane & 15;
    const int a_csel = ((lane >> 4) & 1) << 4;
    const int b_row = (lane & 7) + (((lane >> 4) & 1) << 3);
    const int b_csel = ((lane >> 3) & 1) << 4;

    for (int t = 0; t < T; ++t) {
        const __half* hsrc = &g_h16[t & 1][0];
        __half* hdst = &g_h16[(t + 1) & 1][0];

        float xgv[4];
        {
            const float* xp = xg + ((size_t)(eb * T + t)) * G + ejg;
#pragma unroll
            for (int q = 0; q < 4; ++q) xgv[q] = __ldg(xp + q * H);
        }

        // h chunk kc: 64 rows x 128 fp16 = 16KB; triple buffered
        auto load_h = [&](int kc, int buf) {
            const uint32_t base = sb + SM_Hb + buf * 16384;
            const char* gp = (const char*)hsrc + kc * 256;
#pragma unroll
            for (int p = 0; p < 2; ++p) {
                int idx = tid + p * 512;          // 0..1023
                int row = idx >> 4;               // 0..63
                int c16 = (idx & 15) << 4;        // 0..240
                cp_async16(base + row * 256 + (c16 ^ ((row & 7) << 4)),
                           gp + (size_t)row * 2048 + c16);
            }
            cp_commit();
        };

        float accH[2][4];
#pragma unroll
        for (int s = 0; s < 2; ++s)
#pragma unroll
            for (int k = 0; k < 4; ++k) accH[s][k] = 0.f;

        load_h(0, 0);
        int buf = 0;
        for (int kc = 0; kc < 8; ++kc) {
            if (kc + 1 < 8) {
                int nb = buf + 1; if (nb == 3) nb = 0;
                load_h(kc + 1, nb);
                cp_wait<1>();
            } else {
                cp_wait<0>();
            }
            __syncthreads();           // single sync per chunk (triple buffer)

            const uint32_t hB  = sb + SM_Hb + buf * 16384;
            const uint32_t wHi = sb + SM_W + kc * 8192;

#pragma unroll
            for (int ks4 = 0; ks4 < 4; ++ks4) {
                const int ks = half * 4 + ks4;
                const int acol = ks * 32 + a_csel;
                const int bcol = ks * 32 + b_csel;
                uint32_t ah[4], bh[4];
                int arow = wm + a_row;
                uint32_t aoff = arow * 256 + (acol ^ ((arow & 7) << 4));
                ldsm4(ah, hB + aoff);
                int brow = wn + b_row;
                uint32_t boff = brow * 256 + (bcol ^ ((brow & 7) << 4));
                ldsm4(bh, wHi + boff);
#pragma unroll
                for (int s = 0; s < 2; ++s)
                    mma16816h(accH[s], ah, &bh[s * 2]);
            }
            if (++buf == 3) buf = 0;
        }

        // stage partials: sres[half][row][40]
        {
            int r0 = wm + (lane >> 2);
            int cb = wn + (lane & 3) * 2;
            float* rp = sres + half * 2560;
#pragma unroll
            for (int s = 0; s < 2; ++s) {
                *(float2*)&rp[r0 * 40 + cb + s * 8]       = make_float2(accH[s][0], accH[s][1]);
                *(float2*)&rp[(r0 + 8) * 40 + cb + s * 8] = make_float2(accH[s][2], accH[s][3]);
            }
        }
        __syncthreads();

        // epilogue: reduce halves + activations + state update + writes
        {
            float iv = sres[eb * 40 + ej]      + sres[2560 + eb * 40 + ej]      + xgv[0];
            float fv = sres[eb * 40 + 8 + ej]  + sres[2560 + eb * 40 + 8 + ej]  + xgv[1];
            float gv = sres[eb * 40 + 16 + ej] + sres[2560 + eb * 40 + 16 + ej] + xgv[2];
            float ov = sres[eb * 40 + 24 + ej] + sres[2560 + eb * 40 + 24 + ej] + xgv[3];
            float ig = 1.f / (1.f + expf(-iv));
            float fg = 1.f / (1.f + expf(-fv));
            float gg = tanhf(gv);
            float og = 1.f / (1.f + expf(-ov));
            float cv = fg * creg + ig * gg;
            creg = cv;
            float hv = og * tanhf(cv);
            hdst[eb * H + ejg] = __float2half_rn(hv);
            __nv_bfloat16 hh = __float2bfloat16(hv);
            size_t yoff = ((size_t)(eb * T + t)) * H + ejg;
            yhi[yoff] = hh;
            ylo[yoff] = __float2bfloat16(hv - __bfloat162float(hh));
            if (t == T - 1) { hT[eb * H + ejg] = hv; cT[eb * H + ejg] = cv; }
        }
        gbar(e0 + 2 + t);
    }
}

// ---------------- launch ----------------
extern "C" void kernel_launch(void* const* d_in, const int* in_sizes, int n_in,
                              void* d_out, int out_size) {
    const float* x    = (const float*)d_in[0];
    const float* h0   = (const float*)d_in[1];
    const float* c0   = (const float*)d_in[2];
    const float* Wih0 = (const float*)d_in[3];
    const float* Whh0 = (const float*)d_in[4];
    const float* b0   = (const float*)d_in[5];
    const float* Wih1 = (const float*)d_in[6];
    const float* Whh1 = (const float*)d_in[7];
    const float* b1   = (const float*)d_in[8];
    const float* Wout = (const float*)d_in[9];
    const float* bout = (const float*)d_in[10];

    float* out     = (float*)d_out;
    float* out_act = out;
    float* out_h   = out + (size_t)M * V;
    float* out_c   = out_h + 2 * B * H;

    float *xg;
    __nv_bfloat16 *ahi, *alo, *whi, *wlo;
    cudaGetSymbolAddress((void**)&xg, g_xg);
    cudaGetSymbolAddress((void**)&ahi, g_act_hi);
    cudaGetSymbolAddress((void**)&alo, g_act_lo);
    cudaGetSymbolAddress((void**)&whi, g_w_hi);
    cudaGetSymbolAddress((void**)&wlo, g_w_lo);

    cudaFuncSetAttribute(gemm_mma, cudaFuncAttributeMaxDynamicSharedMemorySize, (int)SMEM_GM);
    cudaFuncSetAttribute(lstm_rec_tc, cudaFuncAttributeMaxDynamicSharedMemorySize, (int)SMEM_TC);

    // ---- Layer 0 input GEMM: xg = x @ Wih0^T + b0  (K=128) ----
    split_bf16<<<(M * V / 4 + 255) / 256, 256>>>(x, ahi, alo, M * V / 4);
    split_bf16<<<(G * V / 4 + 255) / 256, 256>>>(Wih0, whi, wlo, G * V / 4);
    gemm_mma<<<dim3(G / GM_BN, M / GM_BM), 256, SMEM_GM>>>(ahi, alo, whi, wlo, b0, xg, G, V);
    // ---- Layer 0 recurrence: writes y0 as bf16 hi/lo into act buffers ----
    lstm_rec_tc<<<NCTA, 512, SMEM_TC>>>(xg, Whh0, h0, c0, ahi, alo, out_h, out_c);
    // ---- Layer 1 input GEMM: xg = y0 @ Wih1^T + b1  (K=1024) ----
    split_bf16<<<(G * H / 4 + 255) / 256, 256>>>(Wih1, whi, wlo, G * H / 4);
    gemm_mma<<<dim3(G / GM_BN, M / GM_BM), 256, SMEM_GM>>>(ahi, alo, whi, wlo, b1, xg, G, H);
    // ---- Layer 1 recurrence ----
    lstm_rec_tc<<<NCTA, 512, SMEM_TC>>>(xg, Whh1, h0 + B * H, c0 + B * H, ahi, alo,
                                        out_h + B * H, out_c + B * H);
    // ---- Head: act = y1 @ Wout^T + b_out  (N=128, K=1024) ----
    split_bf16<<<(V * H / 4 + 255) / 256, 256>>>(Wout, whi, wlo, V * H / 4);
    gemm_mma<<<dim3(V / GM_BN, M / GM_BM), 256, SMEM_GM>>>(ahi, alo, whi, wlo, bout, out_act, V, H);
}

// round 16
// speedup vs baseline: 1.5391x; 1.1682x over previous
#include <cuda_runtime.h>
#include <cuda_fp16.h>
#include <cstdint>

#define B 64
#define T 256
#define V 128
#define H 1024
#define G 4096              // 4*H
#define M (B*T)             // 16384
#define NCTA 128

// ---------------- feed-forward fp16 GEMM tile config (BM64xBN128, 2-stage) ----------------
#define GM_BM 64
#define GM_BN 128
#define GM_BK 64
#define GM_A_BYTES (64 * 128)            // 8KB  (64 rows x 64 fp16)
#define GM_B_BYTES (128 * 128)           // 16KB (128 rows x 64 fp16)
#define GM_STAGE (GM_A_BYTES + GM_B_BYTES)   // 24KB
#define SMEM_GM (2 * GM_STAGE)               // 48KB

// ---------------- recurrence smem layout (bytes) ----------------
// W:  [8 kc][32 rows][256B] fp16             -> 64 KB
// H:  [3 buf][64 rows][256B] fp16            -> 48 KB
// RES:[2 half][64][40] fp32                  -> 20 KB
#define SM_W   0
#define SM_Hb  65536
#define SM_RES 114688
#define SMEM_TC (SM_RES + 2 * 64 * 40 * 4)   // 135168

// ---------------- scratch (static device arrays; no cudaMalloc) ----------------
__device__ float g_xg[(size_t)M * G];
__device__ __align__(16) __half g_a16[(size_t)M * H];   // fp16 activations (x, then y0, then y1)
__device__ __align__(16) __half g_w16[(size_t)G * H];   // fp16 weights (per-phase)
__device__ __align__(16) __half g_h16[2][B * H];        // fp16 hidden state, double buffered
__device__ unsigned g_count;
__device__ unsigned g_epoch;

// ---------------- PTX helpers ----------------
__device__ __forceinline__ uint32_t smem_u32(const void* p) {
    uint32_t a;
    asm("{ .reg .u64 t; cvta.to.shared.u64 t, %1; cvt.u32.u64 %0, t; }" : "=r"(a) : "l"(p));
    return a;
}
__device__ __forceinline__ void cp_async16(uint32_t saddr, const void* gaddr) {
    asm volatile("cp.async.cg.shared.global [%0], [%1], 16;" :: "r"(saddr), "l"(gaddr) : "memory");
}
__device__ __forceinline__ void cp_commit() {
    asm volatile("cp.async.commit_group;" ::: "memory");
}
template <int N>
__device__ __forceinline__ void cp_wait() {
    asm volatile("cp.async.wait_group %0;" :: "n"(N) : "memory");
}
__device__ __forceinline__ void ldsm4(uint32_t* r, uint32_t addr) {
    asm volatile("ldmatrix.sync.aligned.m8n8.x4.shared.b16 {%0,%1,%2,%3}, [%4];"
        : "=r"(r[0]), "=r"(r[1]), "=r"(r[2]), "=r"(r[3]) : "r"(addr));
}
__device__ __forceinline__ void mma16816h(float* d, const uint32_t* a, const uint32_t* b) {
    asm volatile("mma.sync.aligned.m16n8k16.row.col.f32.f16.f16.f32 "
        "{%0,%1,%2,%3}, {%4,%5,%6,%7}, {%8,%9}, {%0,%1,%2,%3};"
        : "+f"(d[0]), "+f"(d[1]), "+f"(d[2]), "+f"(d[3])
        : "r"(a[0]), "r"(a[1]), "r"(a[2]), "r"(a[3]), "r"(b[0]), "r"(b[1]));
}

// ---------------- software grid barrier (atomic, single-thread poll) ----------------
__device__ __forceinline__ void gbar(unsigned target) {
    __threadfence();
    __syncthreads();
    if (threadIdx.x == 0) {
        unsigned prev = atomicAdd(&g_count, 1u);
        if (prev == NCTA - 1) {
            g_count = 0u;
            __threadfence();
            *((volatile unsigned*)&g_epoch) = target;
        } else {
            while (*((volatile unsigned*)&g_epoch) != target) { __nanosleep(32); }
            __threadfence();
        }
    }
    __syncthreads();
}

// ---------------- fp32 -> fp16 convert (elementwise) ----------------
__global__ void __launch_bounds__(256) to_fp16(
    const float* __restrict__ in, __half* __restrict__ out, int n4)
{
    int i = blockIdx.x * 256 + threadIdx.x;
    if (i >= n4) return;
    float4 v = ((const float4*)in)[i];
    ((__half2*)out)[2 * i]     = __halves2half2(__float2half_rn(v.x), __float2half_rn(v.y));
    ((__half2*)out)[2 * i + 1] = __halves2half2(__float2half_rn(v.z), __float2half_rn(v.w));
}

// ---------------- fp16 tensor GEMM: C[M,N] = A[M,K] * Bw[N,K]^T + bias ----------------
// 256 threads = 8 warps (2m x 4n), warp tile 32x32, 2-stage cp.async.
__global__ void __launch_bounds__(256, 2) gemm_mma(
    const __half* __restrict__ A, const __half* __restrict__ Bw,
    const float* __restrict__ bias, float* __restrict__ C, int Nn, int Kk)
{
    extern __shared__ char smem[];
    const uint32_t sb = smem_u32(smem);
    const int tid  = threadIdx.x;
    const int wid  = tid >> 5;
    const int lane = tid & 31;
    const int m0 = blockIdx.y * GM_BM;
    const int n0 = blockIdx.x * GM_BN;
    const int wm = (wid >> 2) * 32;
    const int wn = (wid & 3) * 32;

    const char* srcA = (const char*)(A  + (size_t)m0 * Kk);
    const char* srcB = (const char*)(Bw + (size_t)n0 * Kk);
    const size_t rstride = (size_t)Kk * 2;
    const int nk = Kk / GM_BK;

    auto load_chunk = [&](int kt, int buf) {
        const uint32_t base = sb + buf * GM_STAGE;
        {   // A tile: 64 rows x 128B, 512 x 16B = 2 per thread
            const char* gp = srcA + (size_t)kt * 128;
#pragma unroll
            for (int p = 0; p < 2; ++p) {
                int idx = tid + p * 256;
                int row = idx >> 3;
                int c16 = (idx & 7) << 4;
                cp_async16(base + row * 128 + (c16 ^ ((row & 7) << 4)),
                           gp + (size_t)row * rstride + c16);
            }
        }
        {   // B tile: 128 rows x 128B, 1024 x 16B = 4 per thread
            const char* gp = srcB + (size_t)kt * 128;
            const uint32_t tb = base + GM_A_BYTES;
#pragma unroll
            for (int p = 0; p < 4; ++p) {
                int idx = tid + p * 256;
                int row = idx >> 3;
                int c16 = (idx & 7) << 4;
                cp_async16(tb + row * 128 + (c16 ^ ((row & 7) << 4)),
                           gp + (size_t)row * rstride + c16);
            }
        }
        cp_commit();
    };

    float acc[2][4][4];
#pragma unroll
    for (int i = 0; i < 2; ++i)
#pragma unroll
        for (int j = 0; j < 4; ++j)
#pragma unroll
            for (int k = 0; k < 4; ++k) acc[i][j][k] = 0.f;

    load_chunk(0, 0);

    const int a_row = lane & 15;
    const int a_csel = ((lane >> 4) & 1) << 4;
    const int b_row = (lane & 7) + (((lane >> 4) & 1) << 3);
    const int b_csel = ((lane >> 3) & 1) << 4;

    for (int kt = 0; kt < nk; ++kt) {
        const int buf = kt & 1;
        if (kt + 1 < nk) { load_chunk(kt + 1, buf ^ 1); cp_wait<1>(); }
        else             { cp_wait<0>(); }
        __syncthreads();

        const uint32_t aB = sb + buf * GM_STAGE;
        const uint32_t bB = aB + GM_A_BYTES;

#pragma unroll
        for (int ks = 0; ks < 4; ++ks) {
            const int acol = ks * 32 + a_csel;
            const int bcol = ks * 32 + b_csel;
            uint32_t av[2][4], bv[2][4];
#pragma unroll
            for (int mt = 0; mt < 2; ++mt) {
                int row = wm + mt * 16 + a_row;
                ldsm4(av[mt], aB + row * 128 + (acol ^ ((row & 7) << 4)));
            }
#pragma unroll
            for (int np = 0; np < 2; ++np) {
                int row = wn + np * 16 + b_row;
                ldsm4(bv[np], bB + row * 128 + (bcol ^ ((row & 7) << 4)));
            }
#pragma unroll
            for (int mt = 0; mt < 2; ++mt)
#pragma unroll
                for (int np = 0; np < 2; ++np)
#pragma unroll
                    for (int s = 0; s < 2; ++s)
                        mma16816h(acc[mt][np * 2 + s], av[mt], &bv[np][s * 2]);
        }
        __syncthreads();
    }

#pragma unroll
    for (int mt = 0; mt < 2; ++mt) {
        const int rg = m0 + wm + mt * 16 + (lane >> 2);
#pragma unroll
        for (int nt = 0; nt < 4; ++nt) {
            const int cg = n0 + wn + nt * 8 + (lane & 3) * 2;
            const float2 bv = *(const float2*)(bias + cg);
            float2 o0, o1;
            o0.x = acc[mt][nt][0] + bv.x;
            o0.y = acc[mt][nt][1] + bv.y;
            o1.x = acc[mt][nt][2] + bv.x;
            o1.y = acc[mt][nt][3] + bv.y;
            *(float2*)(C + (size_t)rg * Nn + cg) = o0;
            *(float2*)(C + (size_t)(rg + 8) * Nn + cg) = o1;
        }
    }
}

// ---------------- tensor-core persistent LSTM recurrence (fp16 W + fp16 h; R15 core) ----------------
__global__ void __launch_bounds__(512, 1) lstm_rec_tc(
    const float* __restrict__ xg, const float* __restrict__ Whh,
    const float* __restrict__ h0, const float* __restrict__ c0,
    __half* __restrict__ y16,
    float* __restrict__ hT, float* __restrict__ cT)
{
    extern __shared__ char smem[];
    const uint32_t sb = smem_u32(smem);
    float* sres = (float*)(smem + SM_RES);
    const int tid  = threadIdx.x;
    const int wid  = tid >> 5;
    const int lane = tid & 31;
    const int cta  = blockIdx.x;

    const unsigned e0 = *((volatile unsigned*)&g_epoch);

    // ---- prologue: convert this CTA's 32 W_hh rows to fp16 in smem ----
    for (int i = tid; i < 32 * 256; i += 512) {
        int r  = i >> 8;
        int c4 = i & 255;
        int gr = (r >> 3) * H + cta * 8 + (r & 7);
        float4 v = *(const float4*)(Whh + (size_t)gr * H + c4 * 4);
        int e  = c4 * 4;
        int kc = e >> 7;
        uint32_t bo = (uint32_t)((e & 127) * 2);
        uint32_t off = (uint32_t)(kc * 8192 + r * 256) + (bo ^ (uint32_t)((r & 7) << 4));
        *(__half2*)(smem + SM_W + off) =
            __halves2half2(__float2half_rn(v.x), __float2half_rn(v.y));
        *(__half2*)(smem + SM_W + off + 4) =
            __halves2half2(__float2half_rn(v.z), __float2half_rn(v.w));
    }

    // ---- init: one (b, j) per thread ----
    const int eb = tid >> 3;
    const int ej = tid & 7;
    const int ejg = cta * 8 + ej;
    float creg;
    {
        float hv = h0[eb * H + ejg];
        g_h16[0][eb * H + ejg] = __float2half_rn(hv);
        creg = c0[eb * H + ejg];
    }
    gbar(e0 + 1);

    const int half = wid >> 3;
    const int wq   = wid & 7;
    const int wm = (wq >> 1) * 16;
    const int wn = (wq & 1) * 16;
    const int a_row = lane & 15;
    const int a_csel = ((lane >> 4) & 1) << 4;
    const int b_row = (lane & 7) + (((lane >> 4) & 1) << 3);
    const int b_csel = ((lane >> 3) & 1) << 4;

    for (int t = 0; t < T; ++t) {
        const __half* hsrc = &g_h16[t & 1][0];
        __half* hdst = &g_h16[(t + 1) & 1][0];

        float xgv[4];
        {
            const float* xp = xg + ((size_t)(eb * T + t)) * G + ejg;
#pragma unroll
            for (int q = 0; q < 4; ++q) xgv[q] = __ldg(xp + q * H);
        }

        auto load_h = [&](int kc, int buf) {
            const uint32_t base = sb + SM_Hb + buf * 16384;
            const char* gp = (const char*)hsrc + kc * 256;
#pragma unroll
            for (int p = 0; p < 2; ++p) {
                int idx = tid + p * 512;
                int row = idx >> 4;
                int c16 = (idx & 15) << 4;
                cp_async16(base + row * 256 + (c16 ^ ((row & 7) << 4)),
                           gp + (size_t)row * 2048 + c16);
            }
            cp_commit();
        };

        float accH[2][4];
#pragma unroll
        for (int s = 0; s < 2; ++s)
#pragma unroll
            for (int k = 0; k < 4; ++k) accH[s][k] = 0.f;

        load_h(0, 0);
        int buf = 0;
        for (int kc = 0; kc < 8; ++kc) {
            if (kc + 1 < 8) {
                int nb = buf + 1; if (nb == 3) nb = 0;
                load_h(kc + 1, nb);
                cp_wait<1>();
            } else {
                cp_wait<0>();
            }
            __syncthreads();           // single sync per chunk (triple buffer)

            const uint32_t hB  = sb + SM_Hb + buf * 16384;
            const uint32_t wHi = sb + SM_W + kc * 8192;

#pragma unroll
            for (int ks4 = 0; ks4 < 4; ++ks4) {
                const int ks = half * 4 + ks4;
                const int acol = ks * 32 + a_csel;
                const int bcol = ks * 32 + b_csel;
                uint32_t ah[4], bh[4];
                int arow = wm + a_row;
                ldsm4(ah, hB + arow * 256 + (acol ^ ((arow & 7) << 4)));
                int brow = wn + b_row;
                ldsm4(bh, wHi + brow * 256 + (bcol ^ ((brow & 7) << 4)));
#pragma unroll
                for (int s = 0; s < 2; ++s)
                    mma16816h(accH[s], ah, &bh[s * 2]);
            }
            if (++buf == 3) buf = 0;
        }

        // stage partials: sres[half][row][40]
        {
            int r0 = wm + (lane >> 2);
            int cb = wn + (lane & 3) * 2;
            float* rp = sres + half * 2560;
#pragma unroll
            for (int s = 0; s < 2; ++s) {
                *(float2*)&rp[r0 * 40 + cb + s * 8]       = make_float2(accH[s][0], accH[s][1]);
                *(float2*)&rp[(r0 + 8) * 40 + cb + s * 8] = make_float2(accH[s][2], accH[s][3]);
            }
        }
        __syncthreads();

        // epilogue: reduce halves + activations + state update + fp16 y write
        {
            float iv = sres[eb * 40 + ej]      + sres[2560 + eb * 40 + ej]      + xgv[0];
            float fv = sres[eb * 40 + 8 + ej]  + sres[2560 + eb * 40 + 8 + ej]  + xgv[1];
            float gv = sres[eb * 40 + 16 + ej] + sres[2560 + eb * 40 + 16 + ej] + xgv[2];
            float ov = sres[eb * 40 + 24 + ej] + sres[2560 + eb * 40 + 24 + ej] + xgv[3];
            float ig = 1.f / (1.f + expf(-iv));
            float fg = 1.f / (1.f + expf(-fv));
            float gg = tanhf(gv);
            float og = 1.f / (1.f + expf(-ov));
            float cv = fg * creg + ig * gg;
            creg = cv;
            float hv = og * tanhf(cv);
            __half h16 = __float2half_rn(hv);
            hdst[eb * H + ejg] = h16;
            y16[((size_t)(eb * T + t)) * H + ejg] = h16;
            if (t == T - 1) { hT[eb * H + ejg] = hv; cT[eb * H + ejg] = cv; }
        }
        gbar(e0 + 2 + t);
    }
}

// ---------------- launch ----------------
extern "C" void kernel_launch(void* const* d_in, const int* in_sizes, int n_in,
                              void* d_out, int out_size) {
    const float* x    = (const float*)d_in[0];
    const float* h0   = (const float*)d_in[1];
    const float* c0   = (const float*)d_in[2];
    const float* Wih0 = (const float*)d_in[3];
    const float* Whh0 = (const float*)d_in[4];
    const float* b0   = (const float*)d_in[5];
    const float* Wih1 = (const float*)d_in[6];
    const float* Whh1 = (const float*)d_in[7];
    const float* b1   = (const float*)d_in[8];
    const float* Wout = (const float*)d_in[9];
    const float* bout = (const float*)d_in[10];

    float* out     = (float*)d_out;
    float* out_act = out;
    float* out_h   = out + (size_t)M * V;
    float* out_c   = out_h + 2 * B * H;

    float *xg;
    __half *a16, *w16;
    cudaGetSymbolAddress((void**)&xg, g_xg);
    cudaGetSymbolAddress((void**)&a16, g_a16);
    cudaGetSymbolAddress((void**)&w16, g_w16);

    cudaFuncSetAttribute(gemm_mma, cudaFuncAttributeMaxDynamicSharedMemorySize, (int)SMEM_GM);
    cudaFuncSetAttribute(lstm_rec_tc, cudaFuncAttributeMaxDynamicSharedMemorySize, (int)SMEM_TC);

    // ---- Layer 0 input GEMM: xg = x @ Wih0^T + b0  (K=128) ----
    to_fp16<<<(M * V / 4 + 255) / 256, 256>>>(x, a16, M * V / 4);
    to_fp16<<<(G * V / 4 + 255) / 256, 256>>>(Wih0, w16, G * V / 4);
    gemm_mma<<<dim3(G / GM_BN, M / GM_BM), 256, SMEM_GM>>>(a16, w16, b0, xg, G, V);
    // ---- Layer 0 recurrence: writes y0 directly as fp16 into a16 ----
    lstm_rec_tc<<<NCTA, 512, SMEM_TC>>>(xg, Whh0, h0, c0, a16, out_h, out_c);
    // ---- Layer 1 input GEMM: xg = y0 @ Wih1^T + b1  (K=1024) ----
    to_fp16<<<(G * H / 4 + 255) / 256, 256>>>(Wih1, w16, G * H / 4);
    gemm_mma<<<dim3(G / GM_BN, M / GM_BM), 256, SMEM_GM>>>(a16, w16, b1, xg, G, H);
    // ---- Layer 1 recurrence: writes y1 into a16 (y0 consumed) ----
    lstm_rec_tc<<<NCTA, 512, SMEM_TC>>>(xg, Whh1, h0 + B * H, c0 + B * H, a16,
                                        out_h + B * H, out_c + B * H);
    // ---- Head: act = y1 @ Wout^T + b_out  (N=128, K=1024) ----
    to_fp16<<<(V * H / 4 + 255) / 256, 256>>>(Wout, w16, V * H / 4);
    gemm_mma<<<dim3(V / GM_BN, M / GM_BM), 256, SMEM_GM>>>(a16, w16, bout, out_act, V, H);
}

// round 17
// speedup vs baseline: 1.5547x; 1.0102x over previous
#include <cuda_runtime.h>
#include <cuda_fp16.h>
#include <cstdint>

#define B 64
#define T 256
#define V 128
#define H 1024
#define G 4096              // 4*H
#define M (B*T)             // 16384
#define NCTA 128

// ---------------- feed-forward fp16 GEMM tile config (BM128xBN128, 2-stage) ----------------
#define GM_BM 128
#define GM_BN 128
#define GM_BK 64
#define GM_TILE_BYTES (128 * 128)            // 16KB per operand tile
#define GM_STAGE (2 * GM_TILE_BYTES)         // 32KB (A + B)
#define SMEM_GM (2 * GM_STAGE)               // 64KB -> 2 CTAs/SM

// ---------------- recurrence smem layout (bytes) ----------------
// W:  [8 kc][32 rows][256B] fp16                 -> 64 KB
// H:  [3 buf][64 rows][512B] fp16 (256-col chunk) -> 96 KB
// RES:[2 half][64][40] fp32                       -> 20 KB
#define SM_W   0
#define SM_Hb  65536
#define SM_RES 163840
#define SMEM_TC (SM_RES + 2 * 64 * 40 * 4)   // 184320

// ---------------- scratch (static device arrays; no cudaMalloc) ----------------
__device__ float g_xg[(size_t)M * G];
__device__ __align__(16) __half g_a16[(size_t)M * H];   // fp16 activations (x, y0, y1)
__device__ __align__(16) __half g_w16[(size_t)G * H];   // fp16 weights (per-phase)
__device__ __align__(16) __half g_h16[2][B * H];        // fp16 hidden state, double buffered
__device__ unsigned g_cnt1[16 * 32];    // group counters, 128B apart
__device__ unsigned g_cnt2;             // root counter
__device__ unsigned g_epoch;

// ---------------- PTX helpers ----------------
__device__ __forceinline__ uint32_t smem_u32(const void* p) {
    uint32_t a;
    asm("{ .reg .u64 t; cvta.to.shared.u64 t, %1; cvt.u32.u64 %0, t; }" : "=r"(a) : "l"(p));
    return a;
}
__device__ __forceinline__ void cp_async16(uint32_t saddr, const void* gaddr) {
    asm volatile("cp.async.cg.shared.global [%0], [%1], 16;" :: "r"(saddr), "l"(gaddr) : "memory");
}
__device__ __forceinline__ void cp_commit() {
    asm volatile("cp.async.commit_group;" ::: "memory");
}
template <int N>
__device__ __forceinline__ void cp_wait() {
    asm volatile("cp.async.wait_group %0;" :: "n"(N) : "memory");
}
__device__ __forceinline__ void ldsm4(uint32_t* r, uint32_t addr) {
    asm volatile("ldmatrix.sync.aligned.m8n8.x4.shared.b16 {%0,%1,%2,%3}, [%4];"
        : "=r"(r[0]), "=r"(r[1]), "=r"(r[2]), "=r"(r[3]) : "r"(addr));
}
__device__ __forceinline__ void mma16816h(float* d, const uint32_t* a, const uint32_t* b) {
    asm volatile("mma.sync.aligned.m16n8k16.row.col.f32.f16.f16.f32 "
        "{%0,%1,%2,%3}, {%4,%5,%6,%7}, {%8,%9}, {%0,%1,%2,%3};"
        : "+f"(d[0]), "+f"(d[1]), "+f"(d[2]), "+f"(d[3])
        : "r"(a[0]), "r"(a[1]), "r"(a[2]), "r"(a[3]), "r"(b[0]), "r"(b[1]));
}

// ---------------- two-level tree grid barrier (16 groups x 8 CTAs) ----------------
__device__ __forceinline__ void gbar(unsigned target) {
    __threadfence();
    __syncthreads();
    if (threadIdx.x == 0) {
        const int g = (blockIdx.x >> 3) * 32;       // 128B-spread group slot
        if (atomicAdd(&g_cnt1[g], 1u) == 7u) {
            g_cnt1[g] = 0u;
            if (atomicAdd(&g_cnt2, 1u) == 15u) {
                g_cnt2 = 0u;
                __threadfence();
                *((volatile unsigned*)&g_epoch) = target;
            }
        }
        while (*((volatile unsigned*)&g_epoch) != target) { __nanosleep(32); }
        __threadfence();
    }
    __syncthreads();
}

// ---------------- fp32 -> fp16 convert (elementwise) ----------------
__global__ void __launch_bounds__(256) to_fp16(
    const float* __restrict__ in, __half* __restrict__ out, int n4)
{
    int i = blockIdx.x * 256 + threadIdx.x;
    if (i >= n4) return;
    float4 v = ((const float4*)in)[i];
    ((__half2*)out)[2 * i]     = __halves2half2(__float2half_rn(v.x), __float2half_rn(v.y));
    ((__half2*)out)[2 * i + 1] = __halves2half2(__float2half_rn(v.z), __float2half_rn(v.w));
}

// ---------------- fp16 tensor GEMM: C[M,N] = A[M,K] * Bw[N,K]^T + bias ----------------
// 256 threads = 8 warps (2m x 4n), warp tile 64x32, CTA tile 128x128, 2-stage.
__global__ void __launch_bounds__(256, 2) gemm_mma(
    const __half* __restrict__ A, const __half* __restrict__ Bw,
    const float* __restrict__ bias, float* __restrict__ C, int Nn, int Kk)
{
    extern __shared__ char smem[];
    const uint32_t sb = smem_u32(smem);
    const int tid  = threadIdx.x;
    const int wid  = tid >> 5;
    const int lane = tid & 31;
    const int m0 = blockIdx.y * GM_BM;
    const int n0 = blockIdx.x * GM_BN;
    const int wm = (wid >> 2) * 64;
    const int wn = (wid & 3) * 32;

    const char* srcA = (const char*)(A  + (size_t)m0 * Kk);
    const char* srcB = (const char*)(Bw + (size_t)n0 * Kk);
    const size_t rstride = (size_t)Kk * 2;
    const int nk = Kk / GM_BK;

    auto load_chunk = [&](int kt, int buf) {
        const uint32_t base = sb + buf * GM_STAGE;
        const char* gps[2] = { srcA + (size_t)kt * 128, srcB + (size_t)kt * 128 };
#pragma unroll
        for (int tgt = 0; tgt < 2; ++tgt) {
            const uint32_t tb = base + tgt * GM_TILE_BYTES;
            const char* gp = gps[tgt];
#pragma unroll
            for (int p = 0; p < 4; ++p) {
                int idx = tid + p * 256;            // 0..1023
                int row = idx >> 3;
                int c16 = (idx & 7) << 4;
                cp_async16(tb + row * 128 + (c16 ^ ((row & 7) << 4)),
                           gp + (size_t)row * rstride + c16);
            }
        }
        cp_commit();
    };

    float acc[4][4][4];
#pragma unroll
    for (int i = 0; i < 4; ++i)
#pragma unroll
        for (int j = 0; j < 4; ++j)
#pragma unroll
            for (int k = 0; k < 4; ++k) acc[i][j][k] = 0.f;

    load_chunk(0, 0);

    const int a_row = lane & 15;
    const int a_csel = ((lane >> 4) & 1) << 4;
    const int b_row = (lane & 7) + (((lane >> 4) & 1) << 3);
    const int b_csel = ((lane >> 3) & 1) << 4;

    for (int kt = 0; kt < nk; ++kt) {
        const int buf = kt & 1;
        if (kt + 1 < nk) { load_chunk(kt + 1, buf ^ 1); cp_wait<1>(); }
        else             { cp_wait<0>(); }
        __syncthreads();

        const uint32_t aB = sb + buf * GM_STAGE;
        const uint32_t bB = aB + GM_TILE_BYTES;

#pragma unroll
        for (int ks = 0; ks < 4; ++ks) {
            const int acol = ks * 32 + a_csel;
            const int bcol = ks * 32 + b_csel;
            uint32_t av[4][4], bv[2][4];
#pragma unroll
            for (int mt = 0; mt < 4; ++mt) {
                int row = wm + mt * 16 + a_row;
                ldsm4(av[mt], aB + row * 128 + (acol ^ ((row & 7) << 4)));
            }
#pragma unroll
            for (int np = 0; np < 2; ++np) {
                int row = wn + np * 16 + b_row;
                ldsm4(bv[np], bB + row * 128 + (bcol ^ ((row & 7) << 4)));
            }
#pragma unroll
            for (int mt = 0; mt < 4; ++mt)
#pragma unroll
                for (int np = 0; np < 2; ++np)
#pragma unroll
                    for (int s = 0; s < 2; ++s)
                        mma16816h(acc[mt][np * 2 + s], av[mt], &bv[np][s * 2]);
        }
        __syncthreads();
    }

#pragma unroll
    for (int mt = 0; mt < 4; ++mt) {
        const int rg = m0 + wm + mt * 16 + (lane >> 2);
#pragma unroll
        for (int nt = 0; nt < 4; ++nt) {
            const int cg = n0 + wn + nt * 8 + (lane & 3) * 2;
            const float2 bv = *(const float2*)(bias + cg);
            float2 o0, o1;
            o0.x = acc[mt][nt][0] + bv.x;
            o0.y = acc[mt][nt][1] + bv.y;
            o1.x = acc[mt][nt][2] + bv.x;
            o1.y = acc[mt][nt][3] + bv.y;
            *(float2*)(C + (size_t)rg * Nn + cg) = o0;
            *(float2*)(C + (size_t)(rg + 8) * Nn + cg) = o1;
        }
    }
}

// ---------------- tensor-core persistent LSTM recurrence ----------------
// fp16 W + fp16 h; h streamed in 4 chunks of 256 columns (512B rows),
// triple-buffered -> one __syncthreads per chunk; tree barrier per step.
// Each warp half-group uses exactly one W kc-block per chunk: wkc = 2c + half.
__global__ void __launch_bounds__(512, 1) lstm_rec_tc(
    const float* __restrict__ xg, const float* __restrict__ Whh,
    const float* __restrict__ h0, const float* __restrict__ c0,
    __half* __restrict__ y16,
    float* __restrict__ hT, float* __restrict__ cT)
{
    extern __shared__ char smem[];
    const uint32_t sb = smem_u32(smem);
    float* sres = (float*)(smem + SM_RES);
    const int tid  = threadIdx.x;
    const int wid  = tid >> 5;
    const int lane = tid & 31;
    const int cta  = blockIdx.x;

    const unsigned e0 = *((volatile unsigned*)&g_epoch);

    // ---- prologue: convert this CTA's 32 W_hh rows to fp16 in smem ----
    for (int i = tid; i < 32 * 256; i += 512) {
        int r  = i >> 8;
        int c4 = i & 255;
        int gr = (r >> 3) * H + cta * 8 + (r & 7);
        float4 v = *(const float4*)(Whh + (size_t)gr * H + c4 * 4);
        int e  = c4 * 4;
        int kc = e >> 7;
        uint32_t bo = (uint32_t)((e & 127) * 2);
        uint32_t off = (uint32_t)(kc * 8192 + r * 256) + (bo ^ (uint32_t)((r & 7) << 4));
        *(__half2*)(smem + SM_W + off) =
            __halves2half2(__float2half_rn(v.x), __float2half_rn(v.y));
        *(__half2*)(smem + SM_W + off + 4) =
            __halves2half2(__float2half_rn(v.z), __float2half_rn(v.w));
    }

    // ---- init: one (b, j) per thread ----
    const int eb = tid >> 3;
    const int ej = tid & 7;
    const int ejg = cta * 8 + ej;
    float creg;
    {
        float hv = h0[eb * H + ejg];
        g_h16[0][eb * H + ejg] = __float2half_rn(hv);
        creg = c0[eb * H + ejg];
    }
    gbar(e0 + 1);

    const int half = wid >> 3;
    const int wq   = wid & 7;
    const int wm = (wq >> 1) * 16;
    const int wn = (wq & 1) * 16;
    const int a_row = lane & 15;
    const int a_csel = ((lane >> 4) & 1) << 4;
    const int b_row = (lane & 7) + (((lane >> 4) & 1) << 3);
    const int b_csel = ((lane >> 3) & 1) << 4;

    for (int t = 0; t < T; ++t) {
        const __half* hsrc = &g_h16[t & 1][0];
        __half* hdst = &g_h16[(t + 1) & 1][0];

        float xgv[4];
        {
            const float* xp = xg + ((size_t)(eb * T + t)) * G + ejg;
#pragma unroll
            for (int q = 0; q < 4; ++q) xgv[q] = __ldg(xp + q * H);
        }

        // h chunk c: 64 rows x 256 fp16 (512B rows) = 32KB; 2048 x 16B = 4 per thread
        auto load_h = [&](int c, int buf) {
            const uint32_t base = sb + SM_Hb + buf * 32768;
            const char* gp = (const char*)hsrc + c * 512;
#pragma unroll
            for (int p = 0; p < 4; ++p) {
                int idx = tid + p * 512;          // 0..2047
                int row = idx >> 5;               // 0..63
                int c16 = (idx & 31) << 4;        // 0..496
                cp_async16(base + row * 512 + (c16 ^ ((row & 7) << 4)),
                           gp + (size_t)row * 2048 + c16);
            }
            cp_commit();
        };

        float accH[2][4];
#pragma unroll
        for (int s = 0; s < 2; ++s)
#pragma unroll
            for (int k = 0; k < 4; ++k) accH[s][k] = 0.f;

        load_h(0, 0);
        int buf = 0;
        for (int c = 0; c < 4; ++c) {
            if (c + 1 < 4) {
                int nb = buf + 1; if (nb == 3) nb = 0;
                load_h(c + 1, nb);
                cp_wait<1>();
            } else {
                cp_wait<0>();
            }
            __syncthreads();           // single sync per chunk (triple buffer)

            const uint32_t hB = sb + SM_Hb + buf * 32768;
            const uint32_t wB = sb + SM_W + (2 * c + half) * 8192;

#pragma unroll
            for (int ks4 = 0; ks4 < 8; ++ks4) {
                const int acol = (half * 8 + ks4) * 32 + a_csel;   // 0..511
                const int bcol = ks4 * 32 + b_csel;                // 0..255
                uint32_t ah[4], bh[4];
                int arow = wm + a_row;
                ldsm4(ah, hB + arow * 512 + (acol ^ ((arow & 7) << 4)));
                int brow = wn + b_row;
                ldsm4(bh, wB + brow * 256 + (bcol ^ ((brow & 7) << 4)));
#pragma unroll
                for (int s = 0; s < 2; ++s)
                    mma16816h(accH[s], ah, &bh[s * 2]);
            }
            if (++buf == 3) buf = 0;
        }

        // stage partials: sres[half][row][40]
        {
            int r0 = wm + (lane >> 2);
            int cb = wn + (lane & 3) * 2;
            float* rp = sres + half * 2560;
#pragma unroll
            for (int s = 0; s < 2; ++s) {
                *(float2*)&rp[r0 * 40 + cb + s * 8]       = make_float2(accH[s][0], accH[s][1]);
                *(float2*)&rp[(r0 + 8) * 40 + cb + s * 8] = make_float2(accH[s][2], accH[s][3]);
            }
        }
        __syncthreads();

        // epilogue: reduce halves + activations + state update + fp16 y write
        {
            float iv = sres[eb * 40 + ej]      + sres[2560 + eb * 40 + ej]      + xgv[0];
            float fv = sres[eb * 40 + 8 + ej]  + sres[2560 + eb * 40 + 8 + ej]  + xgv[1];
            float gv = sres[eb * 40 + 16 + ej] + sres[2560 + eb * 40 + 16 + ej] + xgv[2];
            float ov = sres[eb * 40 + 24 + ej] + sres[2560 + eb * 40 + 24 + ej] + xgv[3];
            float ig = 1.f / (1.f + expf(-iv));
            float fg = 1.f / (1.f + expf(-fv));
            float gg = tanhf(gv);
            float og = 1.f / (1.f + expf(-ov));
            float cv = fg * creg + ig * gg;
            creg = cv;
            float hv = og * tanhf(cv);
            __half h16 = __float2half_rn(hv);
            hdst[eb * H + ejg] = h16;
            y16[((size_t)(eb * T + t)) * H + ejg] = h16;
            if (t == T - 1) { hT[eb * H + ejg] = hv; cT[eb * H + ejg] = cv; }
        }
        gbar(e0 + 2 + t);
    }
}

// ---------------- launch ----------------
extern "C" void kernel_launch(void* const* d_in, const int* in_sizes, int n_in,
                              void* d_out, int out_size) {
    const float* x    = (const float*)d_in[0];
    const float* h0   = (const float*)d_in[1];
    const float* c0   = (const float*)d_in[2];
    const float* Wih0 = (const float*)d_in[3];
    const float* Whh0 = (const float*)d_in[4];
    const float* b0   = (const float*)d_in[5];
    const float* Wih1 = (const float*)d_in[6];
    const float* Whh1 = (const float*)d_in[7];
    const float* b1   = (const float*)d_in[8];
    const float* Wout = (const float*)d_in[9];
    const float* bout = (const float*)d_in[10];

    float* out     = (float*)d_out;
    float* out_act = out;
    float* out_h   = out + (size_t)M * V;
    float* out_c   = out_h + 2 * B * H;

    float *xg;
    __half *a16, *w16;
    cudaGetSymbolAddress((void**)&xg, g_xg);
    cudaGetSymbolAddress((void**)&a16, g_a16);
    cudaGetSymbolAddress((void**)&w16, g_w16);

    cudaFuncSetAttribute(gemm_mma, cudaFuncAttributeMaxDynamicSharedMemorySize, (int)SMEM_GM);
    cudaFuncSetAttribute(lstm_rec_tc, cudaFuncAttributeMaxDynamicSharedMemorySize, (int)SMEM_TC);

    // ---- Layer 0 input GEMM: xg = x @ Wih0^T + b0  (K=128) ----
    to_fp16<<<(M * V / 4 + 255) / 256, 256>>>(x, a16, M * V / 4);
    to_fp16<<<(G * V / 4 + 255) / 256, 256>>>(Wih0, w16, G * V / 4);
    gemm_mma<<<dim3(G / GM_BN, M / GM_BM), 256, SMEM_GM>>>(a16, w16, b0, xg, G, V);
    // ---- Layer 0 recurrence: writes y0 directly as fp16 into a16 ----
    lstm_rec_tc<<<NCTA, 512, SMEM_TC>>>(xg, Whh0, h0, c0, a16, out_h, out_c);
    // ---- Layer 1 input GEMM: xg = y0 @ Wih1^T + b1  (K=1024) ----
    to_fp16<<<(G * H / 4 + 255) / 256, 256>>>(Wih1, w16, G * H / 4);
    gemm_mma<<<dim3(G / GM_BN, M / GM_BM), 256, SMEM_GM>>>(a16, w16, b1, xg, G, H);
    // ---- Layer 1 recurrence: writes y1 into a16 (y0 consumed) ----
    lstm_rec_tc<<<NCTA, 512, SMEM_TC>>>(xg, Whh1, h0 + B * H, c0 + B * H, a16,
                                        out_h + B * H, out_c + B * H);
    // ---- Head: act = y1 @ Wout^T + b_out  (N=128, K=1024) ----
    to_fp16<<<(V * H / 4 + 255) / 256, 256>>>(Wout, w16, V * H / 4);
    gemm_mma<<<dim3(V / GM_BN, M / GM_BM), 256, SMEM_GM>>>(a16, w16, bout, out_act, V, H);
}